// round 11
// baseline (speedup 1.0000x reference)
#include <cuda_runtime.h>
#include <cuda_fp16.h>
#include <mma.h>
#include <cstdint>
#include <math.h>

using namespace nvcuda;

// ---------------------------------------------------------------------------
// MambaViTBlock: B=8, N=1024 (TOK=8192), D=768, NH=12 (dh=64), MLPH=3072,
//                DI=1536, DS=16, DTR=48, K=4
// Round 11: 3-stage single-barrier tgemm mainloop (2 chunks in flight,
// 1 __syncthreads per chunk, still 2 CTAs/SM at 110.6KB smem);
// vectorized conv (8 channels/thread).
// ---------------------------------------------------------------------------

__device__ __half g_lnh  [8192u * 768u];
__device__ __half g_qkvh [8192u * 2304u];
__device__ __half g_attnh[8192u * 768u];
__device__ __half g_hh   [8192u * 3072u];   // MLP hidden, then mamba xz (half)
__device__ __half g_uh   [8192u * 1536u];
__device__ float  g_dbl  [8192u * 80u];
__device__ __half g_dblh [8192u * 64u];
__device__ float  g_dt   [8192u * 1536u];
__device__ __half g_yh   [8192u * 1536u];
__device__ __half g_wth  [10838016u];

#define WH_AIW  0u
#define WH_AOW  1769472u
#define WH_W1   2359296u
#define WH_W2   4718592u
#define WH_MIN  7077888u
#define WH_MOW  9437184u
#define WH_XPW  10616832u
#define WH_DTW  10739712u

__device__ __forceinline__ float gelu_exact(float v) {
    return 0.5f * v * (1.0f + erff(v * 0.7071067811865475f));
}
__device__ __forceinline__ float softplus_f(float v) {
    return fmaxf(v, 0.0f) + log1pf(expf(-fabsf(v)));
}
__device__ __forceinline__ float silu_f(float v) {
    return v / (1.0f + __expf(-v));
}

__device__ __forceinline__ uint32_t smem_u32(const void* p) {
    uint32_t a;
    asm("{ .reg .u64 t; cvta.to.shared.u64 t, %1; cvt.u32.u64 %0, t; }" : "=r"(a) : "l"(p));
    return a;
}
__device__ __forceinline__ void cp_async16(uint32_t dst, const void* src, int sz) {
    asm volatile("cp.async.ca.shared.global [%0], [%1], 16, %2;"
                 :: "r"(dst), "l"(src), "r"(sz));
}
__device__ __forceinline__ void cp_commit() { asm volatile("cp.async.commit_group;"); }
template<int N>
__device__ __forceinline__ void cp_wait() {
    asm volatile("cp.async.wait_group %0;" :: "n"(N));
}

#define TLDH 72

// ---------------------------------------------------------------------------
// Shared epilogue helper (per 16x16 patch; patch stride 16 floats)
// ---------------------------------------------------------------------------
template<int EPI, bool OH>
__device__ __forceinline__ void epi_patch(
    const float* patch, int lid, int mbase, int nfrag,
    float* Cf, __half* Ch, int ldc,
    const float* bias, const float* resid, int ldr,
    float scale, float gmul)
{
    #pragma unroll
    for (int q = 0; q < 2; q++) {
        const int idx = lid + 32 * q;
        const int r = idx >> 2, c4 = idx & 3;
        float4 v4 = *(const float4*)(patch + r * 16 + c4 * 4);
        const int n = nfrag + c4 * 4;
        const int m = mbase + r;
        float vv[4] = {v4.x, v4.y, v4.z, v4.w};
        #pragma unroll
        for (int qq = 0; qq < 4; qq++) {
            float t = vv[qq] * scale;
            if (EPI >= 1 && EPI <= 4) t += bias[n + qq];
            if (EPI == 3) t = gelu_exact(t);
            if (EPI == 4) t = softplus_f(t);
            if (EPI == 2) t += resid[(long long)m * ldr + n + qq];
            if (EPI == 5) t = resid[(long long)m * ldr + n + qq] + gmul * t;
            vv[qq] = t;
        }
        if (OH) {
            __half2 h0 = __floats2half2_rn(vv[0], vv[1]);
            __half2 h1 = __floats2half2_rn(vv[2], vv[3]);
            uint2 pk;
            pk.x = *(uint32_t*)&h0; pk.y = *(uint32_t*)&h1;
            *(uint2*)(Ch + (long long)m * ldc + n) = pk;
        } else {
            *(float4*)(Cf + (long long)m * ldc + n) =
                make_float4(vv[0], vv[1], vv[2], vv[3]);
        }
    }
}

// ---------------------------------------------------------------------------
// tgemm: 128x128 tile, 128 threads (4 warps of 64x64), BK=64.
// 3-stage cp.async pipeline, ONE __syncthreads per K-chunk.
// launch_bounds(128,2): 256-reg budget, 2 CTAs/SM (110.6KB smem each).
// ---------------------------------------------------------------------------
#define TG_STAGEH (2 * 128 * TLDH)          // halves per stage (A tile + B tile)
#define TG_SMEM   (3 * TG_STAGEH * 2)       // 110592 bytes

template<int EPI, bool OH>
__global__ __launch_bounds__(128, 2)
void tgemm(const __half* __restrict__ A, int lda,
           const __half* __restrict__ B, int ldb,
           void* __restrict__ Cv, int ldc,
           int M, int N, int K,
           const float* __restrict__ bias,
           const float* __restrict__ resid, int ldr,
           float scale, const float* __restrict__ gatep)
{
    extern __shared__ __half smh[];
    const uint32_t sb = smem_u32(smh);

    const int tid = threadIdx.x;
    const int wid = tid >> 5, lid = tid & 31;
    const int warpM = wid & 1;
    const int warpN = wid >> 1;

    float*  Cf = (float*)Cv;
    __half* Ch = (__half*)Cv;

    const int m0 = blockIdx.y * 128, n0 = blockIdx.x * 128;
    const int NC = K / 64;

    wmma::fragment<wmma::accumulator, 16, 16, 16, float> acc[4][4];
    #pragma unroll
    for (int i = 0; i < 4; i++)
        #pragma unroll
        for (int j = 0; j < 4; j++) wmma::fill_fragment(acc[i][j], 0.0f);

    auto stage = [&](int c, int buf) {
        const int k0 = c * 64;
        const uint32_t offA = (uint32_t)buf * TG_STAGEH * 2;
        const uint32_t offB = offA + (128 * TLDH) * 2;
        #pragma unroll
        for (int q = 0; q < 8; q++) {
            const int id  = q * 128 + tid;
            const int row = id >> 3, c16 = id & 7;
            const uint32_t so = (uint32_t)(row * (TLDH * 2) + c16 * 16);
            cp_async16(sb + offA + so,
                       A + (long long)(m0 + row) * lda + k0 + c16 * 8, 16);
            const bool bv = (n0 + row) < N;
            const __half* bsrc = bv ? (B + (long long)(n0 + row) * ldb + k0 + c16 * 8) : B;
            cp_async16(sb + offB + so, bsrc, bv ? 16 : 0);
        }
    };

    auto compute = [&](int buf) {
        const __half* Asb = smh + buf * TG_STAGEH;
        const __half* Bsb = Asb + 128 * TLDH;
        #pragma unroll
        for (int kk = 0; kk < 64; kk += 16) {
            wmma::fragment<wmma::matrix_a, 16, 16, 16, __half, wmma::row_major> af[4];
            #pragma unroll
            for (int i = 0; i < 4; i++)
                wmma::load_matrix_sync(af[i], Asb + (warpM * 64 + i * 16) * TLDH + kk, TLDH);
            wmma::fragment<wmma::matrix_b, 16, 16, 16, __half, wmma::col_major> bf[2];
            wmma::load_matrix_sync(bf[0], Bsb + (warpN * 64) * TLDH + kk, TLDH);
            #pragma unroll
            for (int j = 0; j < 4; j++) {
                if (j < 3)
                    wmma::load_matrix_sync(bf[(j + 1) & 1],
                        Bsb + (warpN * 64 + (j + 1) * 16) * TLDH + kk, TLDH);
                #pragma unroll
                for (int i = 0; i < 4; i++)
                    wmma::mma_sync(acc[i][j], af[i], bf[j & 1], acc[i][j]);
            }
        }
    };

    // prologue: commit stages 0 and 1 (empty commit keeps group count static)
    stage(0, 0);
    cp_commit();
    if (NC > 1) stage(1, 1);
    cp_commit();

    for (int c = 0; c < NC; c++) {
        cp_wait<1>();          // stage c has landed (<=1 pending group)
        __syncthreads();       // all warps: buffer c visible, compute(c-1) done
        if (c + 2 < NC) stage(c + 2, (c + 2) % 3);
        cp_commit();
        compute(c % 3);
    }
    __syncthreads();           // before epilogue reuses smem as patch space

    float gmul = 1.0f;
    if (EPI == 5) gmul = 1.0f / (1.0f + __expf(-gatep[0]));
    float* patch = (float*)smh + wid * 256;

    #pragma unroll
    for (int i = 0; i < 4; i++) {
        #pragma unroll
        for (int j = 0; j < 4; j++) {
            const int nfrag = n0 + warpN * 64 + j * 16;
            if (nfrag >= N) continue;
            wmma::store_matrix_sync(patch, acc[i][j], 16, wmma::mem_row_major);
            __syncwarp();
            epi_patch<EPI, OH>(patch, lid, m0 + warpM * 64 + i * 16, nfrag,
                               Cf, Ch, ldc, bias, resid, ldr, scale, gmul);
            __syncwarp();
        }
    }
}

// ---------------------------------------------------------------------------
// Fused flash attention (unchanged from R10)
// ---------------------------------------------------------------------------
#define FA_SMEM 109056
#define FA_OFF_K 18432
#define FA_OFF_V 36864
#define FA_OFF_SF 55296
#define FA_OFF_PH 90112
#define FA_OFF_L 108544

__global__ __launch_bounds__(128, 2)
void flash_attn(const __half* __restrict__ qkv, __half* __restrict__ O)
{
    extern __shared__ __half smh[];
    const uint32_t sb = smem_u32(smh);
    char* smc = (char*)smh;

    const int tid = threadIdx.x;
    const int wid = tid >> 5, lid = tid & 31;
    const int qb = blockIdx.x;
    const int bh = blockIdx.y;
    const int zb = bh / 12, zh = bh % 12;

    const long long TQ = 1024LL * 2304LL;
    const __half* qbase = qkv + (long long)zb * TQ + zh * 64 + (long long)(qb * 128) * 2304;
    const __half* kbase = qkv + 768  + (long long)zb * TQ + zh * 64;
    const __half* vbase = qkv + 1536 + (long long)zb * TQ + zh * 64;

    #pragma unroll
    for (int q = 0; q < 8; q++) {
        const int id = q * 128 + tid;
        const int row = id >> 3, c16 = id & 7;
        cp_async16(sb + (uint32_t)(row * 144 + c16 * 16),
                   qbase + (long long)row * 2304 + c16 * 8, 16);
    }
    auto stageKV = [&](int it, int buf) {
        const long long r0 = (long long)(it * 64);
        const uint32_t offK = FA_OFF_K + (uint32_t)buf * 9216;
        const uint32_t offV = FA_OFF_V + (uint32_t)buf * 9216;
        #pragma unroll
        for (int q = 0; q < 4; q++) {
            const int id = q * 128 + tid;
            const int row = id >> 3, c16 = id & 7;
            const uint32_t so = (uint32_t)(row * 144 + c16 * 16);
            cp_async16(sb + offK + so, kbase + (r0 + row) * 2304 + c16 * 8, 16);
            cp_async16(sb + offV + so, vbase + (r0 + row) * 2304 + c16 * 8, 16);
        }
    };
    stageKV(0, 0);
    cp_commit();

    wmma::fragment<wmma::accumulator, 16, 16, 16, float> o_acc[2][4];
    #pragma unroll
    for (int i = 0; i < 2; i++)
        #pragma unroll
        for (int j = 0; j < 4; j++) wmma::fill_fragment(o_acc[i][j], 0.0f);
    float l = 0.0f;

    const __half* Qw = smh + (wid * 32) * TLDH;
    float* Sf = (float*)(smc + FA_OFF_SF) + wid * (32 * 68);
    __half* Ph = (__half*)(smc + FA_OFF_PH) + wid * (32 * TLDH);

    for (int it = 0; it < 16; it++) {
        if (it + 1 < 16) {
            stageKV(it + 1, (it + 1) & 1);
            cp_commit();
            cp_wait<1>();
        } else {
            cp_wait<0>();
        }
        __syncthreads();

        const __half* Ks = (const __half*)(smc + FA_OFF_K + (it & 1) * 9216);
        const __half* Vs = (const __half*)(smc + FA_OFF_V + (it & 1) * 9216);

        wmma::fragment<wmma::accumulator, 16, 16, 16, float> sa[2][4];
        #pragma unroll
        for (int i = 0; i < 2; i++)
            #pragma unroll
            for (int j = 0; j < 4; j++) wmma::fill_fragment(sa[i][j], 0.0f);
        #pragma unroll
        for (int kk = 0; kk < 4; kk++) {
            wmma::fragment<wmma::matrix_a, 16, 16, 16, __half, wmma::row_major> aq[2];
            wmma::load_matrix_sync(aq[0], Qw + kk * 16, TLDH);
            wmma::load_matrix_sync(aq[1], Qw + 16 * TLDH + kk * 16, TLDH);
            #pragma unroll
            for (int j = 0; j < 4; j++) {
                wmma::fragment<wmma::matrix_b, 16, 16, 16, __half, wmma::col_major> bk;
                wmma::load_matrix_sync(bk, Ks + (j * 16) * TLDH + kk * 16, TLDH);
                wmma::mma_sync(sa[0][j], aq[0], bk, sa[0][j]);
                wmma::mma_sync(sa[1][j], aq[1], bk, sa[1][j]);
            }
        }
        #pragma unroll
        for (int i = 0; i < 2; i++)
            #pragma unroll
            for (int j = 0; j < 4; j++) {
                #pragma unroll
                for (int e = 0; e < 8; e++)
                    sa[i][j].x[e] = __expf(sa[i][j].x[e] * 0.125f);
                wmma::store_matrix_sync(Sf + (i * 16) * 68 + j * 16, sa[i][j], 68,
                                        wmma::mem_row_major);
            }
        __syncwarp();
        {
            const float* srow = Sf + lid * 68;
            __half* prow = Ph + lid * TLDH;
            float sum = 0.0f;
            #pragma unroll
            for (int c = 0; c < 64; c += 4) {
                float4 v = *(const float4*)(srow + c);
                sum += (v.x + v.y) + (v.z + v.w);
                *(__half2*)(prow + c)     = __floats2half2_rn(v.x, v.y);
                *(__half2*)(prow + c + 2) = __floats2half2_rn(v.z, v.w);
            }
            l += sum;
        }
        __syncwarp();
        #pragma unroll
        for (int kk = 0; kk < 4; kk++) {
            wmma::fragment<wmma::matrix_a, 16, 16, 16, __half, wmma::row_major> ap[2];
            wmma::load_matrix_sync(ap[0], Ph + kk * 16, TLDH);
            wmma::load_matrix_sync(ap[1], Ph + 16 * TLDH + kk * 16, TLDH);
            #pragma unroll
            for (int j = 0; j < 4; j++) {
                wmma::fragment<wmma::matrix_b, 16, 16, 16, __half, wmma::row_major> bv;
                wmma::load_matrix_sync(bv, Vs + (kk * 16) * TLDH + j * 16, TLDH);
                wmma::mma_sync(o_acc[0][j], ap[0], bv, o_acc[0][j]);
                wmma::mma_sync(o_acc[1][j], ap[1], bv, o_acc[1][j]);
            }
        }
        __syncthreads();
    }

    float* l_sm = (float*)(smc + FA_OFF_L);
    l_sm[wid * 32 + lid] = l;
    __syncwarp();

    float* patch = Sf;
    const long long orow0 = (long long)zb * 1024 + qb * 128 + wid * 32;
    #pragma unroll
    for (int i = 0; i < 2; i++) {
        #pragma unroll
        for (int j = 0; j < 4; j++) {
            wmma::store_matrix_sync(patch, o_acc[i][j], 16, wmma::mem_row_major);
            __syncwarp();
            #pragma unroll
            for (int q = 0; q < 2; q++) {
                const int idx = lid + 32 * q;
                const int r = idx >> 2, c4 = idx & 3;
                float4 v = *(const float4*)(patch + r * 16 + c4 * 4);
                const float linv = 1.0f / l_sm[wid * 32 + i * 16 + r];
                __half2 h0 = __floats2half2_rn(v.x * linv, v.y * linv);
                __half2 h1 = __floats2half2_rn(v.z * linv, v.w * linv);
                uint2 pk;
                pk.x = *(uint32_t*)&h0; pk.y = *(uint32_t*)&h1;
                const long long m = orow0 + i * 16 + r;
                const int n = zh * 64 + j * 16 + c4 * 4;
                *(uint2*)(O + m * 768 + n) = pk;
            }
            __syncwarp();
        }
    }
}

// ---------------------------------------------------------------------------
// preps / LN / conv / scan
// ---------------------------------------------------------------------------
__global__ __launch_bounds__(256)
void transpose_f2h(const float* __restrict__ in, int ldi,
                   __half* __restrict__ out, int ldo, int R, int C)
{
    __shared__ float t[32][33];
    const int r0 = blockIdx.y * 32, c0 = blockIdx.x * 32;
    const int tx = threadIdx.x & 31, ty = threadIdx.x >> 5;
    #pragma unroll
    for (int i = 0; i < 32; i += 8) {
        const int r = r0 + ty + i, c = c0 + tx;
        t[ty + i][tx] = (r < R && c < C) ? in[(long long)r * ldi + c] : 0.f;
    }
    __syncthreads();
    #pragma unroll
    for (int i = 0; i < 32; i += 8) {
        const int r = c0 + ty + i, c = r0 + tx;
        if (r < C && c < R) out[(long long)r * ldo + c] = __float2half_rn(t[tx][ty + i]);
    }
}

__global__ __launch_bounds__(256)
void cast_f2h(const float* __restrict__ in, __half* __restrict__ out, int n)
{
    int i = blockIdx.x * 256 + threadIdx.x;
    if (i < n) out[i] = __float2half_rn(in[i]);
}

__global__ __launch_bounds__(256)
void dtw_prep(const float* __restrict__ dtw, __half* __restrict__ out)
{
    int i = blockIdx.x * 256 + threadIdx.x;
    int n = i >> 6, k = i & 63;
    out[i] = (k < 48) ? __float2half_rn(dtw[k * 1536 + n]) : __half(0.f);
}

__global__ __launch_bounds__(256)
void dbl_prep(const float* __restrict__ dbl, __half* __restrict__ out)
{
    int i = blockIdx.x * 256 + threadIdx.x;
    int r = i >> 6, c = i & 63;
    out[i] = (c < 48) ? __float2half_rn(dbl[r * 80 + c]) : __half(0.f);
}

__global__ __launch_bounds__(256)
void ln_kernel(const float* __restrict__ x, const float* __restrict__ g,
               const float* __restrict__ b, __half* __restrict__ y)
{
    long long row = blockIdx.x;
    const float* xr = x + row * 768;
    __half* yr = y + row * 768;
    int tid = threadIdx.x;

    float v0 = xr[tid], v1 = xr[tid + 256], v2 = xr[tid + 512];
    float s  = v0 + v1 + v2;
    float ss = v0 * v0 + v1 * v1 + v2 * v2;

    #pragma unroll
    for (int o = 16; o; o >>= 1) {
        s  += __shfl_xor_sync(0xffffffffu, s, o);
        ss += __shfl_xor_sync(0xffffffffu, ss, o);
    }
    __shared__ float sh_s[8], sh_ss[8];
    int w = tid >> 5, l = tid & 31;
    if (l == 0) { sh_s[w] = s; sh_ss[w] = ss; }
    __syncthreads();
    if (w == 0) {
        float s2  = (l < 8) ? sh_s[l]  : 0.f;
        float ss2 = (l < 8) ? sh_ss[l] : 0.f;
        #pragma unroll
        for (int o = 4; o; o >>= 1) {
            s2  += __shfl_xor_sync(0xffffffffu, s2, o);
            ss2 += __shfl_xor_sync(0xffffffffu, ss2, o);
        }
        if (l == 0) { sh_s[0] = s2; sh_ss[0] = ss2; }
    }
    __syncthreads();
    float mean = sh_s[0] * (1.0f / 768.0f);
    float var  = sh_ss[0] * (1.0f / 768.0f) - mean * mean;
    float rstd = rsqrtf(var + 1e-5f);

    yr[tid]       = __float2half_rn((v0 - mean) * rstd * g[tid]       + b[tid]);
    yr[tid + 256] = __float2half_rn((v1 - mean) * rstd * g[tid + 256] + b[tid + 256]);
    yr[tid + 512] = __float2half_rn((v2 - mean) * rstd * g[tid + 512] + b[tid + 512]);
}

// conv over half xz; 8 channels per thread, 16B vector loads
__global__ __launch_bounds__(256)
void conv_silu_kernel(const __half* __restrict__ xz, const float* __restrict__ cw,
                      const float* __restrict__ cb, __half* __restrict__ uh)
{
    int idx = blockIdx.x * 256 + threadIdx.x;   // < 8192*192
    int dg  = idx % 192;
    int tok = idx / 192;
    int t   = tok & 1023;
    const int d0 = dg * 8;

    float acc[8];
    #pragma unroll
    for (int e = 0; e < 8; e++) acc[e] = cb[d0 + e];

    const __half* base = xz + (long long)tok * 3072 + d0;
    #pragma unroll
    for (int j = 0; j < 4; j++) {
        int tt = t - 3 + j;
        if (tt >= 0) {
            uint4 pk = *(const uint4*)(base + (long long)(j - 3) * 3072);
            const __half2* hp = (const __half2*)&pk;
            #pragma unroll
            for (int e = 0; e < 4; e++) {
                float2 f = __half22float2(hp[e]);
                acc[2 * e]     = fmaf(f.x, cw[(d0 + 2 * e) * 4 + j],     acc[2 * e]);
                acc[2 * e + 1] = fmaf(f.y, cw[(d0 + 2 * e + 1) * 4 + j], acc[2 * e + 1]);
            }
        }
    }
    uint4 opk;
    __half2* op = (__half2*)&opk;
    #pragma unroll
    for (int e = 0; e < 4; e++)
        op[e] = __floats2half2_rn(silu_f(acc[2 * e]), silu_f(acc[2 * e + 1]));
    *(uint4*)(uh + (long long)tok * 1536 + d0) = opk;
}

// scan over half u / half xz-res
__global__ __launch_bounds__(256)
void scan_kernel(const float* __restrict__ dt, const float* __restrict__ dbl,
                 const __half* __restrict__ u, const __half* __restrict__ xz,
                 const float* __restrict__ Alog, const float* __restrict__ Dp,
                 __half* __restrict__ y)
{
    int gg = blockIdx.x * 16 + (threadIdx.x >> 4);
    int s  = threadIdx.x & 15;
    int d  = gg % 1536, b = gg / 1536;

    float A  = -expf(Alog[d * 16 + s]);
    float Dv = Dp[d];
    float h  = 0.0f;
    long long tokbase = (long long)b * 1024;

    for (int t = 0; t < 1024; t++) {
        long long tok = tokbase + t;
        float dtv = dt[tok * 1536 + d];
        float uv  = __half2float(u[tok * 1536 + d]);
        float Bv  = dbl[tok * 80 + 48 + s];
        float Cv  = dbl[tok * 80 + 64 + s];
        float dA  = __expf(dtv * A);
        h = fmaf(dA, h, dtv * Bv * uv);
        float part = h * Cv;
        part += __shfl_xor_sync(0xffffffffu, part, 8, 16);
        part += __shfl_xor_sync(0xffffffffu, part, 4, 16);
        part += __shfl_xor_sync(0xffffffffu, part, 2, 16);
        part += __shfl_xor_sync(0xffffffffu, part, 1, 16);
        if (s == 0) {
            float rv = __half2float(xz[tok * 3072 + 1536 + d]);
            y[tok * 1536 + d] = __float2half_rn((part + uv * Dv) * silu_f(rv));
        }
    }
}

// ---------------------------------------------------------------------------
// Host orchestration
// ---------------------------------------------------------------------------
extern "C" void kernel_launch(void* const* d_in, const int* in_sizes, int n_in,
                              void* d_out, int out_size)
{
    const float* x    = (const float*)d_in[0];
    const float* n1g  = (const float*)d_in[1];
    const float* n1b  = (const float*)d_in[2];
    const float* aiw  = (const float*)d_in[3];
    const float* aib  = (const float*)d_in[4];
    const float* aow  = (const float*)d_in[5];
    const float* aob  = (const float*)d_in[6];
    const float* n2g  = (const float*)d_in[7];
    const float* n2b  = (const float*)d_in[8];
    const float* w1   = (const float*)d_in[9];
    const float* b1   = (const float*)d_in[10];
    const float* w2   = (const float*)d_in[11];
    const float* b2   = (const float*)d_in[12];
    const float* n3g  = (const float*)d_in[13];
    const float* n3b  = (const float*)d_in[14];
    const float* minw = (const float*)d_in[15];
    const float* cw   = (const float*)d_in[16];
    const float* cb   = (const float*)d_in[17];
    const float* xpw  = (const float*)d_in[18];
    const float* dtw  = (const float*)d_in[19];
    const float* dtbi = (const float*)d_in[20];
    const float* alog = (const float*)d_in[21];
    const float* dpar = (const float*)d_in[22];
    const float* mow  = (const float*)d_in[23];
    const float* gate = (const float*)d_in[24];
    float* out = (float*)d_out;

    __half *lnh, *qkvh, *attnh, *hh, *uh, *dblh, *yh, *wth;
    float  *dbl, *gdt;
    cudaGetSymbolAddress((void**)&lnh,   g_lnh);
    cudaGetSymbolAddress((void**)&qkvh,  g_qkvh);
    cudaGetSymbolAddress((void**)&attnh, g_attnh);
    cudaGetSymbolAddress((void**)&hh,    g_hh);
    cudaGetSymbolAddress((void**)&uh,    g_uh);
    cudaGetSymbolAddress((void**)&dbl,   g_dbl);
    cudaGetSymbolAddress((void**)&dblh,  g_dblh);
    cudaGetSymbolAddress((void**)&gdt,   g_dt);
    cudaGetSymbolAddress((void**)&yh,    g_yh);
    cudaGetSymbolAddress((void**)&wth,   g_wth);

    cudaFuncSetAttribute(tgemm<0, true>,  cudaFuncAttributeMaxDynamicSharedMemorySize, TG_SMEM);
    cudaFuncSetAttribute(tgemm<0, false>, cudaFuncAttributeMaxDynamicSharedMemorySize, TG_SMEM);
    cudaFuncSetAttribute(tgemm<1, true>,  cudaFuncAttributeMaxDynamicSharedMemorySize, TG_SMEM);
    cudaFuncSetAttribute(tgemm<2, false>, cudaFuncAttributeMaxDynamicSharedMemorySize, TG_SMEM);
    cudaFuncSetAttribute(tgemm<3, true>,  cudaFuncAttributeMaxDynamicSharedMemorySize, TG_SMEM);
    cudaFuncSetAttribute(tgemm<4, false>, cudaFuncAttributeMaxDynamicSharedMemorySize, TG_SMEM);
    cudaFuncSetAttribute(tgemm<5, false>, cudaFuncAttributeMaxDynamicSharedMemorySize, TG_SMEM);
    cudaFuncSetAttribute(flash_attn,      cudaFuncAttributeMaxDynamicSharedMemorySize, FA_SMEM);

    // launch order: 0 cast_aiw, 1 cast_aow, 2 ln1, 3 QKV gemm, 4 flash, 5 outproj
    cast_f2h<<<(2304 * 768 + 255) / 256, 256>>>(aiw, wth + WH_AIW, 2304 * 768);   // 0
    cast_f2h<<<(768 * 768 + 255) / 256, 256>>>(aow, wth + WH_AOW, 768 * 768);     // 1
    ln_kernel<<<8192, 256>>>(x, n1g, n1b, lnh);                                   // 2

    // 3) QKV = LN1 @ attn_in_w^T + b
    tgemm<1, true><<<dim3(18, 64, 1), 128, TG_SMEM>>>(
        lnh, 768, wth + WH_AIW, 768, qkvh, 2304,
        8192, 2304, 768, aib, nullptr, 0, 1.0f, nullptr);

    // 4) fused attention
    flash_attn<<<dim3(8, 96), 128, FA_SMEM>>>(qkvh, attnh);

    // 5) x = x_in + O @ attn_out_w^T + b
    tgemm<2, false><<<dim3(6, 64, 1), 128, TG_SMEM>>>(
        attnh, 768, wth + WH_AOW, 768, out, 768,
        8192, 768, 768, aob, x, 768, 1.0f, nullptr);

    // remaining weight preps
    transpose_f2h<<<dim3(96, 24, 1), 256>>>(w1, 3072, wth + WH_W1, 768, 768, 3072);
    transpose_f2h<<<dim3(24, 96, 1), 256>>>(w2, 768, wth + WH_W2, 3072, 3072, 768);
    transpose_f2h<<<dim3(96, 24, 1), 256>>>(minw, 3072, wth + WH_MIN, 768, 768, 3072);
    transpose_f2h<<<dim3(24, 48, 1), 256>>>(mow, 768, wth + WH_MOW, 1536, 1536, 768);
    transpose_f2h<<<dim3(3, 48, 1), 256>>>(xpw, 80, wth + WH_XPW, 1536, 1536, 80);
    dtw_prep<<<(1536 * 64 + 255) / 256, 256>>>(dtw, wth + WH_DTW);

    // LN2
    ln_kernel<<<8192, 256>>>(out, n2g, n2b, lnh);

    // H = gelu(LN2 @ W1 + b1) -> half
    tgemm<3, true><<<dim3(24, 64, 1), 128, TG_SMEM>>>(
        lnh, 768, wth + WH_W1, 768, hh, 3072,
        8192, 3072, 768, b1, nullptr, 0, 1.0f, nullptr);

    // x += H @ W2 + b2
    tgemm<2, false><<<dim3(6, 64, 1), 128, TG_SMEM>>>(
        hh, 3072, wth + WH_W2, 3072, out, 768,
        8192, 768, 3072, b2, out, 768, 1.0f, nullptr);

    // LN3
    ln_kernel<<<8192, 256>>>(out, n3g, n3b, lnh);

    // xz = LN3 @ m_in_w -> half (reuses hh)
    tgemm<0, true><<<dim3(24, 64, 1), 128, TG_SMEM>>>(
        lnh, 768, wth + WH_MIN, 768, hh, 3072,
        8192, 3072, 768, nullptr, nullptr, 0, 1.0f, nullptr);

    // u = silu(conv(xz[:, :1536]) + cb) -> half
    conv_silu_kernel<<<6144, 256>>>(hh, cw, cb, uh);

    // dbl = u @ xproj_w -> float
    tgemm<0, false><<<dim3(1, 64, 1), 128, TG_SMEM>>>(
        uh, 1536, wth + WH_XPW, 1536, dbl, 80,
        8192, 80, 1536, nullptr, nullptr, 0, 1.0f, nullptr);

    // dbl[:, :48] -> half padded [8192,64]
    dbl_prep<<<(8192 * 64 + 255) / 256, 256>>>(dbl, dblh);

    // dt = softplus(dbl48 @ dt_w + dt_b) -> float
    tgemm<4, false><<<dim3(12, 64, 1), 128, TG_SMEM>>>(
        dblh, 64, wth + WH_DTW, 64, gdt, 1536,
        8192, 1536, 64, dtbi, nullptr, 0, 1.0f, nullptr);

    // selective scan + (u*D) + *silu(res) -> half
    scan_kernel<<<768, 256>>>(gdt, dbl, uh, hh, alog, dpar, yh);

    // out = x + sigmoid(gate) * (y @ m_out_w)
    tgemm<5, false><<<dim3(6, 64, 1), 128, TG_SMEM>>>(
        yh, 1536, wth + WH_MOW, 1536, out, 768,
        8192, 768, 1536, nullptr, out, 768, 1.0f, gate);
}

// round 12
// speedup vs baseline: 1.0558x; 1.0558x over previous
#include <cuda_runtime.h>
#include <cuda_fp16.h>
#include <mma.h>
#include <cstdint>
#include <math.h>

using namespace nvcuda;

// ---------------------------------------------------------------------------
// MambaViTBlock: B=8, N=1024 (TOK=8192), D=768, NH=12 (dh=64), MLPH=3072,
//                DI=1536, DS=16, DTR=48, K=4
// Round 12: revert tgemm mainloop to measured-best R10 structure (2-stage,
// double barrier, launch_bounds(128,2)); keep R11 vectorized conv.
// ---------------------------------------------------------------------------

__device__ __half g_lnh  [8192u * 768u];
__device__ __half g_qkvh [8192u * 2304u];
__device__ __half g_attnh[8192u * 768u];
__device__ __half g_hh   [8192u * 3072u];   // MLP hidden, then mamba xz (half)
__device__ __half g_uh   [8192u * 1536u];
__device__ float  g_dbl  [8192u * 80u];
__device__ __half g_dblh [8192u * 64u];
__device__ float  g_dt   [8192u * 1536u];
__device__ __half g_yh   [8192u * 1536u];
__device__ __half g_wth  [10838016u];

#define WH_AIW  0u
#define WH_AOW  1769472u
#define WH_W1   2359296u
#define WH_W2   4718592u
#define WH_MIN  7077888u
#define WH_MOW  9437184u
#define WH_XPW  10616832u
#define WH_DTW  10739712u

__device__ __forceinline__ float gelu_exact(float v) {
    return 0.5f * v * (1.0f + erff(v * 0.7071067811865475f));
}
__device__ __forceinline__ float softplus_f(float v) {
    return fmaxf(v, 0.0f) + log1pf(expf(-fabsf(v)));
}
__device__ __forceinline__ float silu_f(float v) {
    return v / (1.0f + __expf(-v));
}

__device__ __forceinline__ uint32_t smem_u32(const void* p) {
    uint32_t a;
    asm("{ .reg .u64 t; cvta.to.shared.u64 t, %1; cvt.u32.u64 %0, t; }" : "=r"(a) : "l"(p));
    return a;
}
__device__ __forceinline__ void cp_async16(uint32_t dst, const void* src, int sz) {
    asm volatile("cp.async.ca.shared.global [%0], [%1], 16, %2;"
                 :: "r"(dst), "l"(src), "r"(sz));
}
__device__ __forceinline__ void cp_commit() { asm volatile("cp.async.commit_group;"); }
template<int N>
__device__ __forceinline__ void cp_wait() {
    asm volatile("cp.async.wait_group %0;" :: "n"(N));
}

#define TLDH 72

// ---------------------------------------------------------------------------
// Shared epilogue helper (per 16x16 patch; patch stride 16 floats)
// ---------------------------------------------------------------------------
template<int EPI, bool OH>
__device__ __forceinline__ void epi_patch(
    const float* patch, int lid, int mbase, int nfrag,
    float* Cf, __half* Ch, int ldc,
    const float* bias, const float* resid, int ldr,
    float scale, float gmul)
{
    #pragma unroll
    for (int q = 0; q < 2; q++) {
        const int idx = lid + 32 * q;
        const int r = idx >> 2, c4 = idx & 3;
        float4 v4 = *(const float4*)(patch + r * 16 + c4 * 4);
        const int n = nfrag + c4 * 4;
        const int m = mbase + r;
        float vv[4] = {v4.x, v4.y, v4.z, v4.w};
        #pragma unroll
        for (int qq = 0; qq < 4; qq++) {
            float t = vv[qq] * scale;
            if (EPI >= 1 && EPI <= 4) t += bias[n + qq];
            if (EPI == 3) t = gelu_exact(t);
            if (EPI == 4) t = softplus_f(t);
            if (EPI == 2) t += resid[(long long)m * ldr + n + qq];
            if (EPI == 5) t = resid[(long long)m * ldr + n + qq] + gmul * t;
            vv[qq] = t;
        }
        if (OH) {
            __half2 h0 = __floats2half2_rn(vv[0], vv[1]);
            __half2 h1 = __floats2half2_rn(vv[2], vv[3]);
            uint2 pk;
            pk.x = *(uint32_t*)&h0; pk.y = *(uint32_t*)&h1;
            *(uint2*)(Ch + (long long)m * ldc + n) = pk;
        } else {
            *(float4*)(Cf + (long long)m * ldc + n) =
                make_float4(vv[0], vv[1], vv[2], vv[3]);
        }
    }
}

// ---------------------------------------------------------------------------
// tgemm: 128x128 tile, 128 threads (4 warps of 64x64), BK=64, 2-stage.
// launch_bounds(128,2): 256-reg budget -> ptxas fragment prefetching.
// (R10 structure — measured best: tensor 53.5%, QKV 89us.)
// ---------------------------------------------------------------------------
#define TG_SMEM (2 * 2 * 128 * TLDH * 2)   // 73728 B

template<int EPI, bool OH>
__global__ __launch_bounds__(128, 2)
void tgemm(const __half* __restrict__ A, int lda,
           const __half* __restrict__ B, int ldb,
           void* __restrict__ Cv, int ldc,
           int M, int N, int K,
           const float* __restrict__ bias,
           const float* __restrict__ resid, int ldr,
           float scale, const float* __restrict__ gatep)
{
    extern __shared__ __half smh[];
    const uint32_t sb = smem_u32(smh);

    const int tid = threadIdx.x;
    const int wid = tid >> 5, lid = tid & 31;
    const int warpM = wid & 1;
    const int warpN = wid >> 1;

    float*  Cf = (float*)Cv;
    __half* Ch = (__half*)Cv;

    const int m0 = blockIdx.y * 128, n0 = blockIdx.x * 128;
    const int NC = K / 64;

    wmma::fragment<wmma::accumulator, 16, 16, 16, float> acc[4][4];
    #pragma unroll
    for (int i = 0; i < 4; i++)
        #pragma unroll
        for (int j = 0; j < 4; j++) wmma::fill_fragment(acc[i][j], 0.0f);

    auto stage = [&](int c, int buf) {
        const int k0 = c * 64;
        const uint32_t offA = (uint32_t)buf * (2 * 128 * TLDH) * 2;
        const uint32_t offB = offA + (128 * TLDH) * 2;
        #pragma unroll
        for (int q = 0; q < 8; q++) {
            const int id  = q * 128 + tid;
            const int row = id >> 3, c16 = id & 7;
            const uint32_t so = (uint32_t)(row * (TLDH * 2) + c16 * 16);
            cp_async16(sb + offA + so,
                       A + (long long)(m0 + row) * lda + k0 + c16 * 8, 16);
            const bool bv = (n0 + row) < N;
            const __half* bsrc = bv ? (B + (long long)(n0 + row) * ldb + k0 + c16 * 8) : B;
            cp_async16(sb + offB + so, bsrc, bv ? 16 : 0);
        }
    };

    auto compute = [&](int buf) {
        const __half* Asb = smh + buf * (2 * 128 * TLDH);
        const __half* Bsb = Asb + 128 * TLDH;
        #pragma unroll
        for (int kk = 0; kk < 64; kk += 16) {
            wmma::fragment<wmma::matrix_a, 16, 16, 16, __half, wmma::row_major> af[4];
            #pragma unroll
            for (int i = 0; i < 4; i++)
                wmma::load_matrix_sync(af[i], Asb + (warpM * 64 + i * 16) * TLDH + kk, TLDH);
            wmma::fragment<wmma::matrix_b, 16, 16, 16, __half, wmma::col_major> bf[2];
            wmma::load_matrix_sync(bf[0], Bsb + (warpN * 64) * TLDH + kk, TLDH);
            #pragma unroll
            for (int j = 0; j < 4; j++) {
                if (j < 3)
                    wmma::load_matrix_sync(bf[(j + 1) & 1],
                        Bsb + (warpN * 64 + (j + 1) * 16) * TLDH + kk, TLDH);
                #pragma unroll
                for (int i = 0; i < 4; i++)
                    wmma::mma_sync(acc[i][j], af[i], bf[j & 1], acc[i][j]);
            }
        }
    };

    stage(0, 0);
    cp_commit();

    for (int c = 0; c < NC; c++) {
        if (c + 1 < NC) {
            stage(c + 1, (c + 1) & 1);
            cp_commit();
            cp_wait<1>();
        } else {
            cp_wait<0>();
        }
        __syncthreads();
        compute(c & 1);
        __syncthreads();
    }

    float gmul = 1.0f;
    if (EPI == 5) gmul = 1.0f / (1.0f + __expf(-gatep[0]));
    float* patch = (float*)smh + wid * 256;

    #pragma unroll
    for (int i = 0; i < 4; i++) {
        #pragma unroll
        for (int j = 0; j < 4; j++) {
            const int nfrag = n0 + warpN * 64 + j * 16;
            if (nfrag >= N) continue;
            wmma::store_matrix_sync(patch, acc[i][j], 16, wmma::mem_row_major);
            __syncwarp();
            epi_patch<EPI, OH>(patch, lid, m0 + warpM * 64 + i * 16, nfrag,
                               Cf, Ch, ldc, bias, resid, ldr, scale, gmul);
            __syncwarp();
        }
    }
}

// ---------------------------------------------------------------------------
// Fused flash attention (R10)
// ---------------------------------------------------------------------------
#define FA_SMEM 109056
#define FA_OFF_K 18432
#define FA_OFF_V 36864
#define FA_OFF_SF 55296
#define FA_OFF_PH 90112
#define FA_OFF_L 108544

__global__ __launch_bounds__(128, 2)
void flash_attn(const __half* __restrict__ qkv, __half* __restrict__ O)
{
    extern __shared__ __half smh[];
    const uint32_t sb = smem_u32(smh);
    char* smc = (char*)smh;

    const int tid = threadIdx.x;
    const int wid = tid >> 5, lid = tid & 31;
    const int qb = blockIdx.x;
    const int bh = blockIdx.y;
    const int zb = bh / 12, zh = bh % 12;

    const long long TQ = 1024LL * 2304LL;
    const __half* qbase = qkv + (long long)zb * TQ + zh * 64 + (long long)(qb * 128) * 2304;
    const __half* kbase = qkv + 768  + (long long)zb * TQ + zh * 64;
    const __half* vbase = qkv + 1536 + (long long)zb * TQ + zh * 64;

    #pragma unroll
    for (int q = 0; q < 8; q++) {
        const int id = q * 128 + tid;
        const int row = id >> 3, c16 = id & 7;
        cp_async16(sb + (uint32_t)(row * 144 + c16 * 16),
                   qbase + (long long)row * 2304 + c16 * 8, 16);
    }
    auto stageKV = [&](int it, int buf) {
        const long long r0 = (long long)(it * 64);
        const uint32_t offK = FA_OFF_K + (uint32_t)buf * 9216;
        const uint32_t offV = FA_OFF_V + (uint32_t)buf * 9216;
        #pragma unroll
        for (int q = 0; q < 4; q++) {
            const int id = q * 128 + tid;
            const int row = id >> 3, c16 = id & 7;
            const uint32_t so = (uint32_t)(row * 144 + c16 * 16);
            cp_async16(sb + offK + so, kbase + (r0 + row) * 2304 + c16 * 8, 16);
            cp_async16(sb + offV + so, vbase + (r0 + row) * 2304 + c16 * 8, 16);
        }
    };
    stageKV(0, 0);
    cp_commit();

    wmma::fragment<wmma::accumulator, 16, 16, 16, float> o_acc[2][4];
    #pragma unroll
    for (int i = 0; i < 2; i++)
        #pragma unroll
        for (int j = 0; j < 4; j++) wmma::fill_fragment(o_acc[i][j], 0.0f);
    float l = 0.0f;

    const __half* Qw = smh + (wid * 32) * TLDH;
    float* Sf = (float*)(smc + FA_OFF_SF) + wid * (32 * 68);
    __half* Ph = (__half*)(smc + FA_OFF_PH) + wid * (32 * TLDH);

    for (int it = 0; it < 16; it++) {
        if (it + 1 < 16) {
            stageKV(it + 1, (it + 1) & 1);
            cp_commit();
            cp_wait<1>();
        } else {
            cp_wait<0>();
        }
        __syncthreads();

        const __half* Ks = (const __half*)(smc + FA_OFF_K + (it & 1) * 9216);
        const __half* Vs = (const __half*)(smc + FA_OFF_V + (it & 1) * 9216);

        wmma::fragment<wmma::accumulator, 16, 16, 16, float> sa[2][4];
        #pragma unroll
        for (int i = 0; i < 2; i++)
            #pragma unroll
            for (int j = 0; j < 4; j++) wmma::fill_fragment(sa[i][j], 0.0f);
        #pragma unroll
        for (int kk = 0; kk < 4; kk++) {
            wmma::fragment<wmma::matrix_a, 16, 16, 16, __half, wmma::row_major> aq[2];
            wmma::load_matrix_sync(aq[0], Qw + kk * 16, TLDH);
            wmma::load_matrix_sync(aq[1], Qw + 16 * TLDH + kk * 16, TLDH);
            #pragma unroll
            for (int j = 0; j < 4; j++) {
                wmma::fragment<wmma::matrix_b, 16, 16, 16, __half, wmma::col_major> bk;
                wmma::load_matrix_sync(bk, Ks + (j * 16) * TLDH + kk * 16, TLDH);
                wmma::mma_sync(sa[0][j], aq[0], bk, sa[0][j]);
                wmma::mma_sync(sa[1][j], aq[1], bk, sa[1][j]);
            }
        }
        #pragma unroll
        for (int i = 0; i < 2; i++)
            #pragma unroll
            for (int j = 0; j < 4; j++) {
                #pragma unroll
                for (int e = 0; e < 8; e++)
                    sa[i][j].x[e] = __expf(sa[i][j].x[e] * 0.125f);
                wmma::store_matrix_sync(Sf + (i * 16) * 68 + j * 16, sa[i][j], 68,
                                        wmma::mem_row_major);
            }
        __syncwarp();
        {
            const float* srow = Sf + lid * 68;
            __half* prow = Ph + lid * TLDH;
            float sum = 0.0f;
            #pragma unroll
            for (int c = 0; c < 64; c += 4) {
                float4 v = *(const float4*)(srow + c);
                sum += (v.x + v.y) + (v.z + v.w);
                *(__half2*)(prow + c)     = __floats2half2_rn(v.x, v.y);
                *(__half2*)(prow + c + 2) = __floats2half2_rn(v.z, v.w);
            }
            l += sum;
        }
        __syncwarp();
        #pragma unroll
        for (int kk = 0; kk < 4; kk++) {
            wmma::fragment<wmma::matrix_a, 16, 16, 16, __half, wmma::row_major> ap[2];
            wmma::load_matrix_sync(ap[0], Ph + kk * 16, TLDH);
            wmma::load_matrix_sync(ap[1], Ph + 16 * TLDH + kk * 16, TLDH);
            #pragma unroll
            for (int j = 0; j < 4; j++) {
                wmma::fragment<wmma::matrix_b, 16, 16, 16, __half, wmma::row_major> bv;
                wmma::load_matrix_sync(bv, Vs + (kk * 16) * TLDH + j * 16, TLDH);
                wmma::mma_sync(o_acc[0][j], ap[0], bv, o_acc[0][j]);
                wmma::mma_sync(o_acc[1][j], ap[1], bv, o_acc[1][j]);
            }
        }
        __syncthreads();
    }

    float* l_sm = (float*)(smc + FA_OFF_L);
    l_sm[wid * 32 + lid] = l;
    __syncwarp();

    float* patch = Sf;
    const long long orow0 = (long long)zb * 1024 + qb * 128 + wid * 32;
    #pragma unroll
    for (int i = 0; i < 2; i++) {
        #pragma unroll
        for (int j = 0; j < 4; j++) {
            wmma::store_matrix_sync(patch, o_acc[i][j], 16, wmma::mem_row_major);
            __syncwarp();
            #pragma unroll
            for (int q = 0; q < 2; q++) {
                const int idx = lid + 32 * q;
                const int r = idx >> 2, c4 = idx & 3;
                float4 v = *(const float4*)(patch + r * 16 + c4 * 4);
                const float linv = 1.0f / l_sm[wid * 32 + i * 16 + r];
                __half2 h0 = __floats2half2_rn(v.x * linv, v.y * linv);
                __half2 h1 = __floats2half2_rn(v.z * linv, v.w * linv);
                uint2 pk;
                pk.x = *(uint32_t*)&h0; pk.y = *(uint32_t*)&h1;
                const long long m = orow0 + i * 16 + r;
                const int n = zh * 64 + j * 16 + c4 * 4;
                *(uint2*)(O + m * 768 + n) = pk;
            }
            __syncwarp();
        }
    }
}

// ---------------------------------------------------------------------------
// preps / LN / conv / scan
// ---------------------------------------------------------------------------
__global__ __launch_bounds__(256)
void transpose_f2h(const float* __restrict__ in, int ldi,
                   __half* __restrict__ out, int ldo, int R, int C)
{
    __shared__ float t[32][33];
    const int r0 = blockIdx.y * 32, c0 = blockIdx.x * 32;
    const int tx = threadIdx.x & 31, ty = threadIdx.x >> 5;
    #pragma unroll
    for (int i = 0; i < 32; i += 8) {
        const int r = r0 + ty + i, c = c0 + tx;
        t[ty + i][tx] = (r < R && c < C) ? in[(long long)r * ldi + c] : 0.f;
    }
    __syncthreads();
    #pragma unroll
    for (int i = 0; i < 32; i += 8) {
        const int r = c0 + ty + i, c = r0 + tx;
        if (r < C && c < R) out[(long long)r * ldo + c] = __float2half_rn(t[tx][ty + i]);
    }
}

__global__ __launch_bounds__(256)
void cast_f2h(const float* __restrict__ in, __half* __restrict__ out, int n)
{
    int i = blockIdx.x * 256 + threadIdx.x;
    if (i < n) out[i] = __float2half_rn(in[i]);
}

__global__ __launch_bounds__(256)
void dtw_prep(const float* __restrict__ dtw, __half* __restrict__ out)
{
    int i = blockIdx.x * 256 + threadIdx.x;
    int n = i >> 6, k = i & 63;
    out[i] = (k < 48) ? __float2half_rn(dtw[k * 1536 + n]) : __half(0.f);
}

__global__ __launch_bounds__(256)
void dbl_prep(const float* __restrict__ dbl, __half* __restrict__ out)
{
    int i = blockIdx.x * 256 + threadIdx.x;
    int r = i >> 6, c = i & 63;
    out[i] = (c < 48) ? __float2half_rn(dbl[r * 80 + c]) : __half(0.f);
}

__global__ __launch_bounds__(256)
void ln_kernel(const float* __restrict__ x, const float* __restrict__ g,
               const float* __restrict__ b, __half* __restrict__ y)
{
    long long row = blockIdx.x;
    const float* xr = x + row * 768;
    __half* yr = y + row * 768;
    int tid = threadIdx.x;

    float v0 = xr[tid], v1 = xr[tid + 256], v2 = xr[tid + 512];
    float s  = v0 + v1 + v2;
    float ss = v0 * v0 + v1 * v1 + v2 * v2;

    #pragma unroll
    for (int o = 16; o; o >>= 1) {
        s  += __shfl_xor_sync(0xffffffffu, s, o);
        ss += __shfl_xor_sync(0xffffffffu, ss, o);
    }
    __shared__ float sh_s[8], sh_ss[8];
    int w = tid >> 5, l = tid & 31;
    if (l == 0) { sh_s[w] = s; sh_ss[w] = ss; }
    __syncthreads();
    if (w == 0) {
        float s2  = (l < 8) ? sh_s[l]  : 0.f;
        float ss2 = (l < 8) ? sh_ss[l] : 0.f;
        #pragma unroll
        for (int o = 4; o; o >>= 1) {
            s2  += __shfl_xor_sync(0xffffffffu, s2, o);
            ss2 += __shfl_xor_sync(0xffffffffu, ss2, o);
        }
        if (l == 0) { sh_s[0] = s2; sh_ss[0] = ss2; }
    }
    __syncthreads();
    float mean = sh_s[0] * (1.0f / 768.0f);
    float var  = sh_ss[0] * (1.0f / 768.0f) - mean * mean;
    float rstd = rsqrtf(var + 1e-5f);

    yr[tid]       = __float2half_rn((v0 - mean) * rstd * g[tid]       + b[tid]);
    yr[tid + 256] = __float2half_rn((v1 - mean) * rstd * g[tid + 256] + b[tid + 256]);
    yr[tid + 512] = __float2half_rn((v2 - mean) * rstd * g[tid + 512] + b[tid + 512]);
}

// conv over half xz; 8 channels per thread, 16B vector loads
__global__ __launch_bounds__(256)
void conv_silu_kernel(const __half* __restrict__ xz, const float* __restrict__ cw,
                      const float* __restrict__ cb, __half* __restrict__ uh)
{
    int idx = blockIdx.x * 256 + threadIdx.x;   // < 8192*192
    int dg  = idx % 192;
    int tok = idx / 192;
    int t   = tok & 1023;
    const int d0 = dg * 8;

    float acc[8];
    #pragma unroll
    for (int e = 0; e < 8; e++) acc[e] = cb[d0 + e];

    const __half* base = xz + (long long)tok * 3072 + d0;
    #pragma unroll
    for (int j = 0; j < 4; j++) {
        int tt = t - 3 + j;
        if (tt >= 0) {
            uint4 pk = *(const uint4*)(base + (long long)(j - 3) * 3072);
            const __half2* hp = (const __half2*)&pk;
            #pragma unroll
            for (int e = 0; e < 4; e++) {
                float2 f = __half22float2(hp[e]);
                acc[2 * e]     = fmaf(f.x, cw[(d0 + 2 * e) * 4 + j],     acc[2 * e]);
                acc[2 * e + 1] = fmaf(f.y, cw[(d0 + 2 * e + 1) * 4 + j], acc[2 * e + 1]);
            }
        }
    }
    uint4 opk;
    __half2* op = (__half2*)&opk;
    #pragma unroll
    for (int e = 0; e < 4; e++)
        op[e] = __floats2half2_rn(silu_f(acc[2 * e]), silu_f(acc[2 * e + 1]));
    *(uint4*)(uh + (long long)tok * 1536 + d0) = opk;
}

// scan over half u / half xz-res
__global__ __launch_bounds__(256)
void scan_kernel(const float* __restrict__ dt, const float* __restrict__ dbl,
                 const __half* __restrict__ u, const __half* __restrict__ xz,
                 const float* __restrict__ Alog, const float* __restrict__ Dp,
                 __half* __restrict__ y)
{
    int gg = blockIdx.x * 16 + (threadIdx.x >> 4);
    int s  = threadIdx.x & 15;
    int d  = gg % 1536, b = gg / 1536;

    float A  = -expf(Alog[d * 16 + s]);
    float Dv = Dp[d];
    float h  = 0.0f;
    long long tokbase = (long long)b * 1024;

    for (int t = 0; t < 1024; t++) {
        long long tok = tokbase + t;
        float dtv = dt[tok * 1536 + d];
        float uv  = __half2float(u[tok * 1536 + d]);
        float Bv  = dbl[tok * 80 + 48 + s];
        float Cv  = dbl[tok * 80 + 64 + s];
        float dA  = __expf(dtv * A);
        h = fmaf(dA, h, dtv * Bv * uv);
        float part = h * Cv;
        part += __shfl_xor_sync(0xffffffffu, part, 8, 16);
        part += __shfl_xor_sync(0xffffffffu, part, 4, 16);
        part += __shfl_xor_sync(0xffffffffu, part, 2, 16);
        part += __shfl_xor_sync(0xffffffffu, part, 1, 16);
        if (s == 0) {
            float rv = __half2float(xz[tok * 3072 + 1536 + d]);
            y[tok * 1536 + d] = __float2half_rn((part + uv * Dv) * silu_f(rv));
        }
    }
}

// ---------------------------------------------------------------------------
// Host orchestration
// ---------------------------------------------------------------------------
extern "C" void kernel_launch(void* const* d_in, const int* in_sizes, int n_in,
                              void* d_out, int out_size)
{
    const float* x    = (const float*)d_in[0];
    const float* n1g  = (const float*)d_in[1];
    const float* n1b  = (const float*)d_in[2];
    const float* aiw  = (const float*)d_in[3];
    const float* aib  = (const float*)d_in[4];
    const float* aow  = (const float*)d_in[5];
    const float* aob  = (const float*)d_in[6];
    const float* n2g  = (const float*)d_in[7];
    const float* n2b  = (const float*)d_in[8];
    const float* w1   = (const float*)d_in[9];
    const float* b1   = (const float*)d_in[10];
    const float* w2   = (const float*)d_in[11];
    const float* b2   = (const float*)d_in[12];
    const float* n3g  = (const float*)d_in[13];
    const float* n3b  = (const float*)d_in[14];
    const float* minw = (const float*)d_in[15];
    const float* cw   = (const float*)d_in[16];
    const float* cb   = (const float*)d_in[17];
    const float* xpw  = (const float*)d_in[18];
    const float* dtw  = (const float*)d_in[19];
    const float* dtbi = (const float*)d_in[20];
    const float* alog = (const float*)d_in[21];
    const float* dpar = (const float*)d_in[22];
    const float* mow  = (const float*)d_in[23];
    const float* gate = (const float*)d_in[24];
    float* out = (float*)d_out;

    __half *lnh, *qkvh, *attnh, *hh, *uh, *dblh, *yh, *wth;
    float  *dbl, *gdt;
    cudaGetSymbolAddress((void**)&lnh,   g_lnh);
    cudaGetSymbolAddress((void**)&qkvh,  g_qkvh);
    cudaGetSymbolAddress((void**)&attnh, g_attnh);
    cudaGetSymbolAddress((void**)&hh,    g_hh);
    cudaGetSymbolAddress((void**)&uh,    g_uh);
    cudaGetSymbolAddress((void**)&dbl,   g_dbl);
    cudaGetSymbolAddress((void**)&dblh,  g_dblh);
    cudaGetSymbolAddress((void**)&gdt,   g_dt);
    cudaGetSymbolAddress((void**)&yh,    g_yh);
    cudaGetSymbolAddress((void**)&wth,   g_wth);

    cudaFuncSetAttribute(tgemm<0, true>,  cudaFuncAttributeMaxDynamicSharedMemorySize, TG_SMEM);
    cudaFuncSetAttribute(tgemm<0, false>, cudaFuncAttributeMaxDynamicSharedMemorySize, TG_SMEM);
    cudaFuncSetAttribute(tgemm<1, true>,  cudaFuncAttributeMaxDynamicSharedMemorySize, TG_SMEM);
    cudaFuncSetAttribute(tgemm<2, false>, cudaFuncAttributeMaxDynamicSharedMemorySize, TG_SMEM);
    cudaFuncSetAttribute(tgemm<3, true>,  cudaFuncAttributeMaxDynamicSharedMemorySize, TG_SMEM);
    cudaFuncSetAttribute(tgemm<4, false>, cudaFuncAttributeMaxDynamicSharedMemorySize, TG_SMEM);
    cudaFuncSetAttribute(tgemm<5, false>, cudaFuncAttributeMaxDynamicSharedMemorySize, TG_SMEM);
    cudaFuncSetAttribute(flash_attn,      cudaFuncAttributeMaxDynamicSharedMemorySize, FA_SMEM);

    // launch order: 0 cast_aiw, 1 cast_aow, 2 ln1, 3 QKV gemm, 4 flash, 5 outproj
    cast_f2h<<<(2304 * 768 + 255) / 256, 256>>>(aiw, wth + WH_AIW, 2304 * 768);   // 0
    cast_f2h<<<(768 * 768 + 255) / 256, 256>>>(aow, wth + WH_AOW, 768 * 768);     // 1
    ln_kernel<<<8192, 256>>>(x, n1g, n1b, lnh);                                   // 2

    // 3) QKV = LN1 @ attn_in_w^T + b
    tgemm<1, true><<<dim3(18, 64, 1), 128, TG_SMEM>>>(
        lnh, 768, wth + WH_AIW, 768, qkvh, 2304,
        8192, 2304, 768, aib, nullptr, 0, 1.0f, nullptr);

    // 4) fused attention
    flash_attn<<<dim3(8, 96), 128, FA_SMEM>>>(qkvh, attnh);

    // 5) x = x_in + O @ attn_out_w^T + b
    tgemm<2, false><<<dim3(6, 64, 1), 128, TG_SMEM>>>(
        attnh, 768, wth + WH_AOW, 768, out, 768,
        8192, 768, 768, aob, x, 768, 1.0f, nullptr);

    // remaining weight preps
    transpose_f2h<<<dim3(96, 24, 1), 256>>>(w1, 3072, wth + WH_W1, 768, 768, 3072);
    transpose_f2h<<<dim3(24, 96, 1), 256>>>(w2, 768, wth + WH_W2, 3072, 3072, 768);
    transpose_f2h<<<dim3(96, 24, 1), 256>>>(minw, 3072, wth + WH_MIN, 768, 768, 3072);
    transpose_f2h<<<dim3(24, 48, 1), 256>>>(mow, 768, wth + WH_MOW, 1536, 1536, 768);
    transpose_f2h<<<dim3(3, 48, 1), 256>>>(xpw, 80, wth + WH_XPW, 1536, 1536, 80);
    dtw_prep<<<(1536 * 64 + 255) / 256, 256>>>(dtw, wth + WH_DTW);

    // LN2
    ln_kernel<<<8192, 256>>>(out, n2g, n2b, lnh);

    // H = gelu(LN2 @ W1 + b1) -> half
    tgemm<3, true><<<dim3(24, 64, 1), 128, TG_SMEM>>>(
        lnh, 768, wth + WH_W1, 768, hh, 3072,
        8192, 3072, 768, b1, nullptr, 0, 1.0f, nullptr);

    // x += H @ W2 + b2
    tgemm<2, false><<<dim3(6, 64, 1), 128, TG_SMEM>>>(
        hh, 3072, wth + WH_W2, 3072, out, 768,
        8192, 768, 3072, b2, out, 768, 1.0f, nullptr);

    // LN3
    ln_kernel<<<8192, 256>>>(out, n3g, n3b, lnh);

    // xz = LN3 @ m_in_w -> half (reuses hh)
    tgemm<0, true><<<dim3(24, 64, 1), 128, TG_SMEM>>>(
        lnh, 768, wth + WH_MIN, 768, hh, 3072,
        8192, 3072, 768, nullptr, nullptr, 0, 1.0f, nullptr);

    // u = silu(conv(xz[:, :1536]) + cb) -> half
    conv_silu_kernel<<<6144, 256>>>(hh, cw, cb, uh);

    // dbl = u @ xproj_w -> float
    tgemm<0, false><<<dim3(1, 64, 1), 128, TG_SMEM>>>(
        uh, 1536, wth + WH_XPW, 1536, dbl, 80,
        8192, 80, 1536, nullptr, nullptr, 0, 1.0f, nullptr);

    // dbl[:, :48] -> half padded [8192,64]
    dbl_prep<<<(8192 * 64 + 255) / 256, 256>>>(dbl, dblh);

    // dt = softplus(dbl48 @ dt_w + dt_b) -> float
    tgemm<4, false><<<dim3(12, 64, 1), 128, TG_SMEM>>>(
        dblh, 64, wth + WH_DTW, 64, gdt, 1536,
        8192, 1536, 64, dtbi, nullptr, 0, 1.0f, nullptr);

    // selective scan + (u*D) + *silu(res) -> half
    scan_kernel<<<768, 256>>>(gdt, dbl, uh, hh, alog, dpar, yh);

    // out = x + sigmoid(gate) * (y @ m_out_w)
    tgemm<5, false><<<dim3(6, 64, 1), 128, TG_SMEM>>>(
        yh, 1536, wth + WH_MOW, 1536, out, 768,
        8192, 768, 1536, nullptr, out, 768, 1.0f, gate);
}

// round 13
// speedup vs baseline: 1.0832x; 1.0260x over previous
#include <cuda_runtime.h>
#include <cuda_fp16.h>
#include <mma.h>
#include <cstdint>
#include <math.h>

using namespace nvcuda;

// ---------------------------------------------------------------------------
// MambaViTBlock: B=8, N=1024 (TOK=8192), D=768, NH=12 (dh=64), MLPH=3072,
//                DI=1536, DS=16, DTR=48, K=4
// Round 13: exact R10 config (best measured: 1903us) + cp.async.cg staging
// (L2-only, bypass L1 — frees L1 bandwidth for LDSM). Scalar conv restored
// (vectorized conv measured 135us slower in R12).
// ---------------------------------------------------------------------------

__device__ __half g_lnh  [8192u * 768u];
__device__ __half g_qkvh [8192u * 2304u];
__device__ __half g_attnh[8192u * 768u];
__device__ __half g_hh   [8192u * 3072u];   // MLP hidden, then mamba xz (half)
__device__ __half g_uh   [8192u * 1536u];
__device__ float  g_dbl  [8192u * 80u];
__device__ __half g_dblh [8192u * 64u];
__device__ float  g_dt   [8192u * 1536u];
__device__ __half g_yh   [8192u * 1536u];
__device__ __half g_wth  [10838016u];

#define WH_AIW  0u
#define WH_AOW  1769472u
#define WH_W1   2359296u
#define WH_W2   4718592u
#define WH_MIN  7077888u
#define WH_MOW  9437184u
#define WH_XPW  10616832u
#define WH_DTW  10739712u

__device__ __forceinline__ float gelu_exact(float v) {
    return 0.5f * v * (1.0f + erff(v * 0.7071067811865475f));
}
__device__ __forceinline__ float softplus_f(float v) {
    return fmaxf(v, 0.0f) + log1pf(expf(-fabsf(v)));
}
__device__ __forceinline__ float silu_f(float v) {
    return v / (1.0f + __expf(-v));
}

__device__ __forceinline__ uint32_t smem_u32(const void* p) {
    uint32_t a;
    asm("{ .reg .u64 t; cvta.to.shared.u64 t, %1; cvt.u32.u64 %0, t; }" : "=r"(a) : "l"(p));
    return a;
}
// .cg: L2-only path, no L1 fill — frees L1 for ldmatrix traffic
__device__ __forceinline__ void cp_async16(uint32_t dst, const void* src, int sz) {
    asm volatile("cp.async.cg.shared.global [%0], [%1], 16, %2;"
                 :: "r"(dst), "l"(src), "r"(sz));
}
__device__ __forceinline__ void cp_commit() { asm volatile("cp.async.commit_group;"); }
template<int N>
__device__ __forceinline__ void cp_wait() {
    asm volatile("cp.async.wait_group %0;" :: "n"(N));
}

#define TLDH 72

// ---------------------------------------------------------------------------
// Shared epilogue helper (per 16x16 patch; patch stride 16 floats)
// ---------------------------------------------------------------------------
template<int EPI, bool OH>
__device__ __forceinline__ void epi_patch(
    const float* patch, int lid, int mbase, int nfrag,
    float* Cf, __half* Ch, int ldc,
    const float* bias, const float* resid, int ldr,
    float scale, float gmul)
{
    #pragma unroll
    for (int q = 0; q < 2; q++) {
        const int idx = lid + 32 * q;
        const int r = idx >> 2, c4 = idx & 3;
        float4 v4 = *(const float4*)(patch + r * 16 + c4 * 4);
        const int n = nfrag + c4 * 4;
        const int m = mbase + r;
        float vv[4] = {v4.x, v4.y, v4.z, v4.w};
        #pragma unroll
        for (int qq = 0; qq < 4; qq++) {
            float t = vv[qq] * scale;
            if (EPI >= 1 && EPI <= 4) t += bias[n + qq];
            if (EPI == 3) t = gelu_exact(t);
            if (EPI == 4) t = softplus_f(t);
            if (EPI == 2) t += resid[(long long)m * ldr + n + qq];
            if (EPI == 5) t = resid[(long long)m * ldr + n + qq] + gmul * t;
            vv[qq] = t;
        }
        if (OH) {
            __half2 h0 = __floats2half2_rn(vv[0], vv[1]);
            __half2 h1 = __floats2half2_rn(vv[2], vv[3]);
            uint2 pk;
            pk.x = *(uint32_t*)&h0; pk.y = *(uint32_t*)&h1;
            *(uint2*)(Ch + (long long)m * ldc + n) = pk;
        } else {
            *(float4*)(Cf + (long long)m * ldc + n) =
                make_float4(vv[0], vv[1], vv[2], vv[3]);
        }
    }
}

// ---------------------------------------------------------------------------
// tgemm: 128x128 tile, 128 threads (4 warps of 64x64), BK=64, 2-stage.
// launch_bounds(128,2): 256-reg budget -> ptxas fragment prefetching.
// ---------------------------------------------------------------------------
#define TG_SMEM (2 * 2 * 128 * TLDH * 2)   // 73728 B

template<int EPI, bool OH>
__global__ __launch_bounds__(128, 2)
void tgemm(const __half* __restrict__ A, int lda,
           const __half* __restrict__ B, int ldb,
           void* __restrict__ Cv, int ldc,
           int M, int N, int K,
           const float* __restrict__ bias,
           const float* __restrict__ resid, int ldr,
           float scale, const float* __restrict__ gatep)
{
    extern __shared__ __half smh[];
    const uint32_t sb = smem_u32(smh);

    const int tid = threadIdx.x;
    const int wid = tid >> 5, lid = tid & 31;
    const int warpM = wid & 1;
    const int warpN = wid >> 1;

    float*  Cf = (float*)Cv;
    __half* Ch = (__half*)Cv;

    const int m0 = blockIdx.y * 128, n0 = blockIdx.x * 128;
    const int NC = K / 64;

    wmma::fragment<wmma::accumulator, 16, 16, 16, float> acc[4][4];
    #pragma unroll
    for (int i = 0; i < 4; i++)
        #pragma unroll
        for (int j = 0; j < 4; j++) wmma::fill_fragment(acc[i][j], 0.0f);

    auto stage = [&](int c, int buf) {
        const int k0 = c * 64;
        const uint32_t offA = (uint32_t)buf * (2 * 128 * TLDH) * 2;
        const uint32_t offB = offA + (128 * TLDH) * 2;
        #pragma unroll
        for (int q = 0; q < 8; q++) {
            const int id  = q * 128 + tid;
            const int row = id >> 3, c16 = id & 7;
            const uint32_t so = (uint32_t)(row * (TLDH * 2) + c16 * 16);
            cp_async16(sb + offA + so,
                       A + (long long)(m0 + row) * lda + k0 + c16 * 8, 16);
            const bool bv = (n0 + row) < N;
            const __half* bsrc = bv ? (B + (long long)(n0 + row) * ldb + k0 + c16 * 8) : B;
            cp_async16(sb + offB + so, bsrc, bv ? 16 : 0);
        }
    };

    auto compute = [&](int buf) {
        const __half* Asb = smh + buf * (2 * 128 * TLDH);
        const __half* Bsb = Asb + 128 * TLDH;
        #pragma unroll
        for (int kk = 0; kk < 64; kk += 16) {
            wmma::fragment<wmma::matrix_a, 16, 16, 16, __half, wmma::row_major> af[4];
            #pragma unroll
            for (int i = 0; i < 4; i++)
                wmma::load_matrix_sync(af[i], Asb + (warpM * 64 + i * 16) * TLDH + kk, TLDH);
            wmma::fragment<wmma::matrix_b, 16, 16, 16, __half, wmma::col_major> bf[2];
            wmma::load_matrix_sync(bf[0], Bsb + (warpN * 64) * TLDH + kk, TLDH);
            #pragma unroll
            for (int j = 0; j < 4; j++) {
                if (j < 3)
                    wmma::load_matrix_sync(bf[(j + 1) & 1],
                        Bsb + (warpN * 64 + (j + 1) * 16) * TLDH + kk, TLDH);
                #pragma unroll
                for (int i = 0; i < 4; i++)
                    wmma::mma_sync(acc[i][j], af[i], bf[j & 1], acc[i][j]);
            }
        }
    };

    stage(0, 0);
    cp_commit();

    for (int c = 0; c < NC; c++) {
        if (c + 1 < NC) {
            stage(c + 1, (c + 1) & 1);
            cp_commit();
            cp_wait<1>();
        } else {
            cp_wait<0>();
        }
        __syncthreads();
        compute(c & 1);
        __syncthreads();
    }

    float gmul = 1.0f;
    if (EPI == 5) gmul = 1.0f / (1.0f + __expf(-gatep[0]));
    float* patch = (float*)smh + wid * 256;

    #pragma unroll
    for (int i = 0; i < 4; i++) {
        #pragma unroll
        for (int j = 0; j < 4; j++) {
            const int nfrag = n0 + warpN * 64 + j * 16;
            if (nfrag >= N) continue;
            wmma::store_matrix_sync(patch, acc[i][j], 16, wmma::mem_row_major);
            __syncwarp();
            epi_patch<EPI, OH>(patch, lid, m0 + warpM * 64 + i * 16, nfrag,
                               Cf, Ch, ldc, bias, resid, ldr, scale, gmul);
            __syncwarp();
        }
    }
}

// ---------------------------------------------------------------------------
// Fused flash attention (R10)
// ---------------------------------------------------------------------------
#define FA_SMEM 109056
#define FA_OFF_K 18432
#define FA_OFF_V 36864
#define FA_OFF_SF 55296
#define FA_OFF_PH 90112
#define FA_OFF_L 108544

__global__ __launch_bounds__(128, 2)
void flash_attn(const __half* __restrict__ qkv, __half* __restrict__ O)
{
    extern __shared__ __half smh[];
    const uint32_t sb = smem_u32(smh);
    char* smc = (char*)smh;

    const int tid = threadIdx.x;
    const int wid = tid >> 5, lid = tid & 31;
    const int qb = blockIdx.x;
    const int bh = blockIdx.y;
    const int zb = bh / 12, zh = bh % 12;

    const long long TQ = 1024LL * 2304LL;
    const __half* qbase = qkv + (long long)zb * TQ + zh * 64 + (long long)(qb * 128) * 2304;
    const __half* kbase = qkv + 768  + (long long)zb * TQ + zh * 64;
    const __half* vbase = qkv + 1536 + (long long)zb * TQ + zh * 64;

    #pragma unroll
    for (int q = 0; q < 8; q++) {
        const int id = q * 128 + tid;
        const int row = id >> 3, c16 = id & 7;
        cp_async16(sb + (uint32_t)(row * 144 + c16 * 16),
                   qbase + (long long)row * 2304 + c16 * 8, 16);
    }
    auto stageKV = [&](int it, int buf) {
        const long long r0 = (long long)(it * 64);
        const uint32_t offK = FA_OFF_K + (uint32_t)buf * 9216;
        const uint32_t offV = FA_OFF_V + (uint32_t)buf * 9216;
        #pragma unroll
        for (int q = 0; q < 4; q++) {
            const int id = q * 128 + tid;
            const int row = id >> 3, c16 = id & 7;
            const uint32_t so = (uint32_t)(row * 144 + c16 * 16);
            cp_async16(sb + offK + so, kbase + (r0 + row) * 2304 + c16 * 8, 16);
            cp_async16(sb + offV + so, vbase + (r0 + row) * 2304 + c16 * 8, 16);
        }
    };
    stageKV(0, 0);
    cp_commit();

    wmma::fragment<wmma::accumulator, 16, 16, 16, float> o_acc[2][4];
    #pragma unroll
    for (int i = 0; i < 2; i++)
        #pragma unroll
        for (int j = 0; j < 4; j++) wmma::fill_fragment(o_acc[i][j], 0.0f);
    float l = 0.0f;

    const __half* Qw = smh + (wid * 32) * TLDH;
    float* Sf = (float*)(smc + FA_OFF_SF) + wid * (32 * 68);
    __half* Ph = (__half*)(smc + FA_OFF_PH) + wid * (32 * TLDH);

    for (int it = 0; it < 16; it++) {
        if (it + 1 < 16) {
            stageKV(it + 1, (it + 1) & 1);
            cp_commit();
            cp_wait<1>();
        } else {
            cp_wait<0>();
        }
        __syncthreads();

        const __half* Ks = (const __half*)(smc + FA_OFF_K + (it & 1) * 9216);
        const __half* Vs = (const __half*)(smc + FA_OFF_V + (it & 1) * 9216);

        wmma::fragment<wmma::accumulator, 16, 16, 16, float> sa[2][4];
        #pragma unroll
        for (int i = 0; i < 2; i++)
            #pragma unroll
            for (int j = 0; j < 4; j++) wmma::fill_fragment(sa[i][j], 0.0f);
        #pragma unroll
        for (int kk = 0; kk < 4; kk++) {
            wmma::fragment<wmma::matrix_a, 16, 16, 16, __half, wmma::row_major> aq[2];
            wmma::load_matrix_sync(aq[0], Qw + kk * 16, TLDH);
            wmma::load_matrix_sync(aq[1], Qw + 16 * TLDH + kk * 16, TLDH);
            #pragma unroll
            for (int j = 0; j < 4; j++) {
                wmma::fragment<wmma::matrix_b, 16, 16, 16, __half, wmma::col_major> bk;
                wmma::load_matrix_sync(bk, Ks + (j * 16) * TLDH + kk * 16, TLDH);
                wmma::mma_sync(sa[0][j], aq[0], bk, sa[0][j]);
                wmma::mma_sync(sa[1][j], aq[1], bk, sa[1][j]);
            }
        }
        #pragma unroll
        for (int i = 0; i < 2; i++)
            #pragma unroll
            for (int j = 0; j < 4; j++) {
                #pragma unroll
                for (int e = 0; e < 8; e++)
                    sa[i][j].x[e] = __expf(sa[i][j].x[e] * 0.125f);
                wmma::store_matrix_sync(Sf + (i * 16) * 68 + j * 16, sa[i][j], 68,
                                        wmma::mem_row_major);
            }
        __syncwarp();
        {
            const float* srow = Sf + lid * 68;
            __half* prow = Ph + lid * TLDH;
            float sum = 0.0f;
            #pragma unroll
            for (int c = 0; c < 64; c += 4) {
                float4 v = *(const float4*)(srow + c);
                sum += (v.x + v.y) + (v.z + v.w);
                *(__half2*)(prow + c)     = __floats2half2_rn(v.x, v.y);
                *(__half2*)(prow + c + 2) = __floats2half2_rn(v.z, v.w);
            }
            l += sum;
        }
        __syncwarp();
        #pragma unroll
        for (int kk = 0; kk < 4; kk++) {
            wmma::fragment<wmma::matrix_a, 16, 16, 16, __half, wmma::row_major> ap[2];
            wmma::load_matrix_sync(ap[0], Ph + kk * 16, TLDH);
            wmma::load_matrix_sync(ap[1], Ph + 16 * TLDH + kk * 16, TLDH);
            #pragma unroll
            for (int j = 0; j < 4; j++) {
                wmma::fragment<wmma::matrix_b, 16, 16, 16, __half, wmma::row_major> bv;
                wmma::load_matrix_sync(bv, Vs + (kk * 16) * TLDH + j * 16, TLDH);
                wmma::mma_sync(o_acc[0][j], ap[0], bv, o_acc[0][j]);
                wmma::mma_sync(o_acc[1][j], ap[1], bv, o_acc[1][j]);
            }
        }
        __syncthreads();
    }

    float* l_sm = (float*)(smc + FA_OFF_L);
    l_sm[wid * 32 + lid] = l;
    __syncwarp();

    float* patch = Sf;
    const long long orow0 = (long long)zb * 1024 + qb * 128 + wid * 32;
    #pragma unroll
    for (int i = 0; i < 2; i++) {
        #pragma unroll
        for (int j = 0; j < 4; j++) {
            wmma::store_matrix_sync(patch, o_acc[i][j], 16, wmma::mem_row_major);
            __syncwarp();
            #pragma unroll
            for (int q = 0; q < 2; q++) {
                const int idx = lid + 32 * q;
                const int r = idx >> 2, c4 = idx & 3;
                float4 v = *(const float4*)(patch + r * 16 + c4 * 4);
                const float linv = 1.0f / l_sm[wid * 32 + i * 16 + r];
                __half2 h0 = __floats2half2_rn(v.x * linv, v.y * linv);
                __half2 h1 = __floats2half2_rn(v.z * linv, v.w * linv);
                uint2 pk;
                pk.x = *(uint32_t*)&h0; pk.y = *(uint32_t*)&h1;
                const long long m = orow0 + i * 16 + r;
                const int n = zh * 64 + j * 16 + c4 * 4;
                *(uint2*)(O + m * 768 + n) = pk;
            }
            __syncwarp();
        }
    }
}

// ---------------------------------------------------------------------------
// preps / LN / conv / scan
// ---------------------------------------------------------------------------
__global__ __launch_bounds__(256)
void transpose_f2h(const float* __restrict__ in, int ldi,
                   __half* __restrict__ out, int ldo, int R, int C)
{
    __shared__ float t[32][33];
    const int r0 = blockIdx.y * 32, c0 = blockIdx.x * 32;
    const int tx = threadIdx.x & 31, ty = threadIdx.x >> 5;
    #pragma unroll
    for (int i = 0; i < 32; i += 8) {
        const int r = r0 + ty + i, c = c0 + tx;
        t[ty + i][tx] = (r < R && c < C) ? in[(long long)r * ldi + c] : 0.f;
    }
    __syncthreads();
    #pragma unroll
    for (int i = 0; i < 32; i += 8) {
        const int r = c0 + ty + i, c = r0 + tx;
        if (r < C && c < R) out[(long long)r * ldo + c] = __float2half_rn(t[tx][ty + i]);
    }
}

__global__ __launch_bounds__(256)
void cast_f2h(const float* __restrict__ in, __half* __restrict__ out, int n)
{
    int i = blockIdx.x * 256 + threadIdx.x;
    if (i < n) out[i] = __float2half_rn(in[i]);
}

__global__ __launch_bounds__(256)
void dtw_prep(const float* __restrict__ dtw, __half* __restrict__ out)
{
    int i = blockIdx.x * 256 + threadIdx.x;
    int n = i >> 6, k = i & 63;
    out[i] = (k < 48) ? __float2half_rn(dtw[k * 1536 + n]) : __half(0.f);
}

__global__ __launch_bounds__(256)
void dbl_prep(const float* __restrict__ dbl, __half* __restrict__ out)
{
    int i = blockIdx.x * 256 + threadIdx.x;
    int r = i >> 6, c = i & 63;
    out[i] = (c < 48) ? __float2half_rn(dbl[r * 80 + c]) : __half(0.f);
}

__global__ __launch_bounds__(256)
void ln_kernel(const float* __restrict__ x, const float* __restrict__ g,
               const float* __restrict__ b, __half* __restrict__ y)
{
    long long row = blockIdx.x;
    const float* xr = x + row * 768;
    __half* yr = y + row * 768;
    int tid = threadIdx.x;

    float v0 = xr[tid], v1 = xr[tid + 256], v2 = xr[tid + 512];
    float s  = v0 + v1 + v2;
    float ss = v0 * v0 + v1 * v1 + v2 * v2;

    #pragma unroll
    for (int o = 16; o; o >>= 1) {
        s  += __shfl_xor_sync(0xffffffffu, s, o);
        ss += __shfl_xor_sync(0xffffffffu, ss, o);
    }
    __shared__ float sh_s[8], sh_ss[8];
    int w = tid >> 5, l = tid & 31;
    if (l == 0) { sh_s[w] = s; sh_ss[w] = ss; }
    __syncthreads();
    if (w == 0) {
        float s2  = (l < 8) ? sh_s[l]  : 0.f;
        float ss2 = (l < 8) ? sh_ss[l] : 0.f;
        #pragma unroll
        for (int o = 4; o; o >>= 1) {
            s2  += __shfl_xor_sync(0xffffffffu, s2, o);
            ss2 += __shfl_xor_sync(0xffffffffu, ss2, o);
        }
        if (l == 0) { sh_s[0] = s2; sh_ss[0] = ss2; }
    }
    __syncthreads();
    float mean = sh_s[0] * (1.0f / 768.0f);
    float var  = sh_ss[0] * (1.0f / 768.0f) - mean * mean;
    float rstd = rsqrtf(var + 1e-5f);

    yr[tid]       = __float2half_rn((v0 - mean) * rstd * g[tid]       + b[tid]);
    yr[tid + 256] = __float2half_rn((v1 - mean) * rstd * g[tid + 256] + b[tid + 256]);
    yr[tid + 512] = __float2half_rn((v2 - mean) * rstd * g[tid + 512] + b[tid + 512]);
}

// conv over half xz; scalar 1 channel/thread (R10 layout — measured best)
__global__ __launch_bounds__(256)
void conv_silu_kernel(const __half* __restrict__ xz, const float* __restrict__ cw,
                      const float* __restrict__ cb, __half* __restrict__ uh)
{
    int idx = blockIdx.x * 256 + threadIdx.x;
    int d   = idx % 1536;
    int tok = idx / 1536;
    int t   = tok & 1023;
    float acc = cb[d];
    const __half* base = xz + (long long)tok * 3072 + d;
    #pragma unroll
    for (int j = 0; j < 4; j++) {
        int tt = t - 3 + j;
        if (tt >= 0)
            acc = fmaf(__half2float(base[(long long)(j - 3) * 3072]), cw[d * 4 + j], acc);
    }
    uh[(long long)tok * 1536 + d] = __float2half_rn(silu_f(acc));
}

// scan over half u / half xz-res
__global__ __launch_bounds__(256)
void scan_kernel(const float* __restrict__ dt, const float* __restrict__ dbl,
                 const __half* __restrict__ u, const __half* __restrict__ xz,
                 const float* __restrict__ Alog, const float* __restrict__ Dp,
                 __half* __restrict__ y)
{
    int gg = blockIdx.x * 16 + (threadIdx.x >> 4);
    int s  = threadIdx.x & 15;
    int d  = gg % 1536, b = gg / 1536;

    float A  = -expf(Alog[d * 16 + s]);
    float Dv = Dp[d];
    float h  = 0.0f;
    long long tokbase = (long long)b * 1024;

    for (int t = 0; t < 1024; t++) {
        long long tok = tokbase + t;
        float dtv = dt[tok * 1536 + d];
        float uv  = __half2float(u[tok * 1536 + d]);
        float Bv  = dbl[tok * 80 + 48 + s];
        float Cv  = dbl[tok * 80 + 64 + s];
        float dA  = __expf(dtv * A);
        h = fmaf(dA, h, dtv * Bv * uv);
        float part = h * Cv;
        part += __shfl_xor_sync(0xffffffffu, part, 8, 16);
        part += __shfl_xor_sync(0xffffffffu, part, 4, 16);
        part += __shfl_xor_sync(0xffffffffu, part, 2, 16);
        part += __shfl_xor_sync(0xffffffffu, part, 1, 16);
        if (s == 0) {
            float rv = __half2float(xz[tok * 3072 + 1536 + d]);
            y[tok * 1536 + d] = __float2half_rn((part + uv * Dv) * silu_f(rv));
        }
    }
}

// ---------------------------------------------------------------------------
// Host orchestration
// ---------------------------------------------------------------------------
extern "C" void kernel_launch(void* const* d_in, const int* in_sizes, int n_in,
                              void* d_out, int out_size)
{
    const float* x    = (const float*)d_in[0];
    const float* n1g  = (const float*)d_in[1];
    const float* n1b  = (const float*)d_in[2];
    const float* aiw  = (const float*)d_in[3];
    const float* aib  = (const float*)d_in[4];
    const float* aow  = (const float*)d_in[5];
    const float* aob  = (const float*)d_in[6];
    const float* n2g  = (const float*)d_in[7];
    const float* n2b  = (const float*)d_in[8];
    const float* w1   = (const float*)d_in[9];
    const float* b1   = (const float*)d_in[10];
    const float* w2   = (const float*)d_in[11];
    const float* b2   = (const float*)d_in[12];
    const float* n3g  = (const float*)d_in[13];
    const float* n3b  = (const float*)d_in[14];
    const float* minw = (const float*)d_in[15];
    const float* cw   = (const float*)d_in[16];
    const float* cb   = (const float*)d_in[17];
    const float* xpw  = (const float*)d_in[18];
    const float* dtw  = (const float*)d_in[19];
    const float* dtbi = (const float*)d_in[20];
    const float* alog = (const float*)d_in[21];
    const float* dpar = (const float*)d_in[22];
    const float* mow  = (const float*)d_in[23];
    const float* gate = (const float*)d_in[24];
    float* out = (float*)d_out;

    __half *lnh, *qkvh, *attnh, *hh, *uh, *dblh, *yh, *wth;
    float  *dbl, *gdt;
    cudaGetSymbolAddress((void**)&lnh,   g_lnh);
    cudaGetSymbolAddress((void**)&qkvh,  g_qkvh);
    cudaGetSymbolAddress((void**)&attnh, g_attnh);
    cudaGetSymbolAddress((void**)&hh,    g_hh);
    cudaGetSymbolAddress((void**)&uh,    g_uh);
    cudaGetSymbolAddress((void**)&dbl,   g_dbl);
    cudaGetSymbolAddress((void**)&dblh,  g_dblh);
    cudaGetSymbolAddress((void**)&gdt,   g_dt);
    cudaGetSymbolAddress((void**)&yh,    g_yh);
    cudaGetSymbolAddress((void**)&wth,   g_wth);

    cudaFuncSetAttribute(tgemm<0, true>,  cudaFuncAttributeMaxDynamicSharedMemorySize, TG_SMEM);
    cudaFuncSetAttribute(tgemm<0, false>, cudaFuncAttributeMaxDynamicSharedMemorySize, TG_SMEM);
    cudaFuncSetAttribute(tgemm<1, true>,  cudaFuncAttributeMaxDynamicSharedMemorySize, TG_SMEM);
    cudaFuncSetAttribute(tgemm<2, false>, cudaFuncAttributeMaxDynamicSharedMemorySize, TG_SMEM);
    cudaFuncSetAttribute(tgemm<3, true>,  cudaFuncAttributeMaxDynamicSharedMemorySize, TG_SMEM);
    cudaFuncSetAttribute(tgemm<4, false>, cudaFuncAttributeMaxDynamicSharedMemorySize, TG_SMEM);
    cudaFuncSetAttribute(tgemm<5, false>, cudaFuncAttributeMaxDynamicSharedMemorySize, TG_SMEM);
    cudaFuncSetAttribute(flash_attn,      cudaFuncAttributeMaxDynamicSharedMemorySize, FA_SMEM);

    // launch order: 0 cast_aiw, 1 cast_aow, 2 ln1, 3 QKV gemm, 4 flash, 5 outproj
    cast_f2h<<<(2304 * 768 + 255) / 256, 256>>>(aiw, wth + WH_AIW, 2304 * 768);   // 0
    cast_f2h<<<(768 * 768 + 255) / 256, 256>>>(aow, wth + WH_AOW, 768 * 768);     // 1
    ln_kernel<<<8192, 256>>>(x, n1g, n1b, lnh);                                   // 2

    // 3) QKV = LN1 @ attn_in_w^T + b
    tgemm<1, true><<<dim3(18, 64, 1), 128, TG_SMEM>>>(
        lnh, 768, wth + WH_AIW, 768, qkvh, 2304,
        8192, 2304, 768, aib, nullptr, 0, 1.0f, nullptr);

    // 4) fused attention
    flash_attn<<<dim3(8, 96), 128, FA_SMEM>>>(qkvh, attnh);

    // 5) x = x_in + O @ attn_out_w^T + b
    tgemm<2, false><<<dim3(6, 64, 1), 128, TG_SMEM>>>(
        attnh, 768, wth + WH_AOW, 768, out, 768,
        8192, 768, 768, aob, x, 768, 1.0f, nullptr);

    // remaining weight preps
    transpose_f2h<<<dim3(96, 24, 1), 256>>>(w1, 3072, wth + WH_W1, 768, 768, 3072);
    transpose_f2h<<<dim3(24, 96, 1), 256>>>(w2, 768, wth + WH_W2, 3072, 3072, 768);
    transpose_f2h<<<dim3(96, 24, 1), 256>>>(minw, 3072, wth + WH_MIN, 768, 768, 3072);
    transpose_f2h<<<dim3(24, 48, 1), 256>>>(mow, 768, wth + WH_MOW, 1536, 1536, 768);
    transpose_f2h<<<dim3(3, 48, 1), 256>>>(xpw, 80, wth + WH_XPW, 1536, 1536, 80);
    dtw_prep<<<(1536 * 64 + 255) / 256, 256>>>(dtw, wth + WH_DTW);

    // LN2
    ln_kernel<<<8192, 256>>>(out, n2g, n2b, lnh);

    // H = gelu(LN2 @ W1 + b1) -> half
    tgemm<3, true><<<dim3(24, 64, 1), 128, TG_SMEM>>>(
        lnh, 768, wth + WH_W1, 768, hh, 3072,
        8192, 3072, 768, b1, nullptr, 0, 1.0f, nullptr);

    // x += H @ W2 + b2
    tgemm<2, false><<<dim3(6, 64, 1), 128, TG_SMEM>>>(
        hh, 3072, wth + WH_W2, 3072, out, 768,
        8192, 768, 3072, b2, out, 768, 1.0f, nullptr);

    // LN3
    ln_kernel<<<8192, 256>>>(out, n3g, n3b, lnh);

    // xz = LN3 @ m_in_w -> half (reuses hh)
    tgemm<0, true><<<dim3(24, 64, 1), 128, TG_SMEM>>>(
        lnh, 768, wth + WH_MIN, 768, hh, 3072,
        8192, 3072, 768, nullptr, nullptr, 0, 1.0f, nullptr);

    // u = silu(conv(xz[:, :1536]) + cb) -> half
    conv_silu_kernel<<<49152, 256>>>(hh, cw, cb, uh);

    // dbl = u @ xproj_w -> float
    tgemm<0, false><<<dim3(1, 64, 1), 128, TG_SMEM>>>(
        uh, 1536, wth + WH_XPW, 1536, dbl, 80,
        8192, 80, 1536, nullptr, nullptr, 0, 1.0f, nullptr);

    // dbl[:, :48] -> half padded [8192,64]
    dbl_prep<<<(8192 * 64 + 255) / 256, 256>>>(dbl, dblh);

    // dt = softplus(dbl48 @ dt_w + dt_b) -> float
    tgemm<4, false><<<dim3(12, 64, 1), 128, TG_SMEM>>>(
        dblh, 64, wth + WH_DTW, 64, gdt, 1536,
        8192, 1536, 64, dtbi, nullptr, 0, 1.0f, nullptr);

    // selective scan + (u*D) + *silu(res) -> half
    scan_kernel<<<768, 256>>>(gdt, dbl, uh, hh, alog, dpar, yh);

    // out = x + sigmoid(gate) * (y @ m_out_w)
    tgemm<5, false><<<dim3(6, 64, 1), 128, TG_SMEM>>>(
        yh, 1536, wth + WH_MOW, 1536, out, 768,
        8192, 768, 1536, nullptr, out, 768, 1.0f, gate);
}

// round 14
// speedup vs baseline: 1.1090x; 1.0238x over previous
#include <cuda_runtime.h>
#include <cuda_fp16.h>
#include <mma.h>
#include <cstdint>
#include <math.h>

using namespace nvcuda;

// ---------------------------------------------------------------------------
// MambaViTBlock: B=8, N=1024 (TOK=8192), D=768, NH=12 (dh=64), MLPH=3072,
//                DI=1536, DS=16, DTR=48, K=4
// Round 14: exact R10 config (best: 1903us, cp.async.ca) + K-split x4 on the
// under-occupied xproj GEMM (64 -> 256 CTAs) with fused partial-sum + pad.
// ---------------------------------------------------------------------------

__device__ __half g_lnh  [8192u * 768u];
__device__ __half g_qkvh [8192u * 2304u];
__device__ __half g_attnh[8192u * 768u];
__device__ __half g_hh   [8192u * 3072u];   // MLP hidden, then mamba xz (half)
__device__ __half g_uh   [8192u * 1536u];
__device__ float  g_dbl  [8192u * 80u];     // final xproj out (dt_raw | B | C)
__device__ __half g_dblh [8192u * 64u];     // dbl[:, :48] padded to 64 (half)
__device__ float  g_dt   [8192u * 1536u];   // ALSO reused: xproj K-split partials
__device__ __half g_yh   [8192u * 1536u];
__device__ __half g_wth  [10838016u];

#define WH_AIW  0u
#define WH_AOW  1769472u
#define WH_W1   2359296u
#define WH_W2   4718592u
#define WH_MIN  7077888u
#define WH_MOW  9437184u
#define WH_XPW  10616832u
#define WH_DTW  10739712u

__device__ __forceinline__ float gelu_exact(float v) {
    return 0.5f * v * (1.0f + erff(v * 0.7071067811865475f));
}
__device__ __forceinline__ float softplus_f(float v) {
    return fmaxf(v, 0.0f) + log1pf(expf(-fabsf(v)));
}
__device__ __forceinline__ float silu_f(float v) {
    return v / (1.0f + __expf(-v));
}

__device__ __forceinline__ uint32_t smem_u32(const void* p) {
    uint32_t a;
    asm("{ .reg .u64 t; cvta.to.shared.u64 t, %1; cvt.u32.u64 %0, t; }" : "=r"(a) : "l"(p));
    return a;
}
__device__ __forceinline__ void cp_async16(uint32_t dst, const void* src, int sz) {
    asm volatile("cp.async.ca.shared.global [%0], [%1], 16, %2;"
                 :: "r"(dst), "l"(src), "r"(sz));
}
__device__ __forceinline__ void cp_commit() { asm volatile("cp.async.commit_group;"); }
template<int N>
__device__ __forceinline__ void cp_wait() {
    asm volatile("cp.async.wait_group %0;" :: "n"(N));
}

#define TLDH 72

// ---------------------------------------------------------------------------
// Shared epilogue helper (per 16x16 patch; patch stride 16 floats)
// ---------------------------------------------------------------------------
template<int EPI, bool OH>
__device__ __forceinline__ void epi_patch(
    const float* patch, int lid, int mbase, int nfrag,
    float* Cf, __half* Ch, int ldc,
    const float* bias, const float* resid, int ldr,
    float scale, float gmul)
{
    #pragma unroll
    for (int q = 0; q < 2; q++) {
        const int idx = lid + 32 * q;
        const int r = idx >> 2, c4 = idx & 3;
        float4 v4 = *(const float4*)(patch + r * 16 + c4 * 4);
        const int n = nfrag + c4 * 4;
        const int m = mbase + r;
        float vv[4] = {v4.x, v4.y, v4.z, v4.w};
        #pragma unroll
        for (int qq = 0; qq < 4; qq++) {
            float t = vv[qq] * scale;
            if (EPI >= 1 && EPI <= 4) t += bias[n + qq];
            if (EPI == 3) t = gelu_exact(t);
            if (EPI == 4) t = softplus_f(t);
            if (EPI == 2) t += resid[(long long)m * ldr + n + qq];
            if (EPI == 5) t = resid[(long long)m * ldr + n + qq] + gmul * t;
            vv[qq] = t;
        }
        if (OH) {
            __half2 h0 = __floats2half2_rn(vv[0], vv[1]);
            __half2 h1 = __floats2half2_rn(vv[2], vv[3]);
            uint2 pk;
            pk.x = *(uint32_t*)&h0; pk.y = *(uint32_t*)&h1;
            *(uint2*)(Ch + (long long)m * ldc + n) = pk;
        } else {
            *(float4*)(Cf + (long long)m * ldc + n) =
                make_float4(vv[0], vv[1], vv[2], vv[3]);
        }
    }
}

// ---------------------------------------------------------------------------
// tgemm: 128x128 tile, 128 threads (4 warps of 64x64), BK=64, 2-stage.
// launch_bounds(128,2): 256-reg budget -> ptxas fragment prefetching.
// Optional K-split over grid.z: A col offset zAoff, C elem offset zCoff.
// ---------------------------------------------------------------------------
#define TG_SMEM (2 * 2 * 128 * TLDH * 2)   // 73728 B

template<int EPI, bool OH>
__global__ __launch_bounds__(128, 2)
void tgemm(const __half* __restrict__ A, int lda,
           const __half* __restrict__ B, int ldb,
           void* __restrict__ Cv, int ldc,
           int M, int N, int K,
           const float* __restrict__ bias,
           const float* __restrict__ resid, int ldr,
           float scale, const float* __restrict__ gatep,
           int zAoff, long long zCoff)
{
    extern __shared__ __half smh[];
    const uint32_t sb = smem_u32(smh);

    const int tid = threadIdx.x;
    const int wid = tid >> 5, lid = tid & 31;
    const int warpM = wid & 1;
    const int warpN = wid >> 1;

    A += (long long)blockIdx.z * zAoff;          // K-split column offset
    B += (long long)blockIdx.z * zAoff;
    float*  Cf = (float*)Cv  + (OH ? 0 : blockIdx.z * zCoff);
    __half* Ch = (__half*)Cv + (OH ? blockIdx.z * zCoff : 0);

    const int m0 = blockIdx.y * 128, n0 = blockIdx.x * 128;
    const int NC = K / 64;

    wmma::fragment<wmma::accumulator, 16, 16, 16, float> acc[4][4];
    #pragma unroll
    for (int i = 0; i < 4; i++)
        #pragma unroll
        for (int j = 0; j < 4; j++) wmma::fill_fragment(acc[i][j], 0.0f);

    auto stage = [&](int c, int buf) {
        const int k0 = c * 64;
        const uint32_t offA = (uint32_t)buf * (2 * 128 * TLDH) * 2;
        const uint32_t offB = offA + (128 * TLDH) * 2;
        #pragma unroll
        for (int q = 0; q < 8; q++) {
            const int id  = q * 128 + tid;
            const int row = id >> 3, c16 = id & 7;
            const uint32_t so = (uint32_t)(row * (TLDH * 2) + c16 * 16);
            cp_async16(sb + offA + so,
                       A + (long long)(m0 + row) * lda + k0 + c16 * 8, 16);
            const bool bv = (n0 + row) < N;
            const __half* bsrc = bv ? (B + (long long)(n0 + row) * ldb + k0 + c16 * 8) : B;
            cp_async16(sb + offB + so, bsrc, bv ? 16 : 0);
        }
    };

    auto compute = [&](int buf) {
        const __half* Asb = smh + buf * (2 * 128 * TLDH);
        const __half* Bsb = Asb + 128 * TLDH;
        #pragma unroll
        for (int kk = 0; kk < 64; kk += 16) {
            wmma::fragment<wmma::matrix_a, 16, 16, 16, __half, wmma::row_major> af[4];
            #pragma unroll
            for (int i = 0; i < 4; i++)
                wmma::load_matrix_sync(af[i], Asb + (warpM * 64 + i * 16) * TLDH + kk, TLDH);
            wmma::fragment<wmma::matrix_b, 16, 16, 16, __half, wmma::col_major> bf[2];
            wmma::load_matrix_sync(bf[0], Bsb + (warpN * 64) * TLDH + kk, TLDH);
            #pragma unroll
            for (int j = 0; j < 4; j++) {
                if (j < 3)
                    wmma::load_matrix_sync(bf[(j + 1) & 1],
                        Bsb + (warpN * 64 + (j + 1) * 16) * TLDH + kk, TLDH);
                #pragma unroll
                for (int i = 0; i < 4; i++)
                    wmma::mma_sync(acc[i][j], af[i], bf[j & 1], acc[i][j]);
            }
        }
    };

    stage(0, 0);
    cp_commit();

    for (int c = 0; c < NC; c++) {
        if (c + 1 < NC) {
            stage(c + 1, (c + 1) & 1);
            cp_commit();
            cp_wait<1>();
        } else {
            cp_wait<0>();
        }
        __syncthreads();
        compute(c & 1);
        __syncthreads();
    }

    float gmul = 1.0f;
    if (EPI == 5) gmul = 1.0f / (1.0f + __expf(-gatep[0]));
    float* patch = (float*)smh + wid * 256;

    #pragma unroll
    for (int i = 0; i < 4; i++) {
        #pragma unroll
        for (int j = 0; j < 4; j++) {
            const int nfrag = n0 + warpN * 64 + j * 16;
            if (nfrag >= N) continue;
            wmma::store_matrix_sync(patch, acc[i][j], 16, wmma::mem_row_major);
            __syncwarp();
            epi_patch<EPI, OH>(patch, lid, m0 + warpM * 64 + i * 16, nfrag,
                               Cf, Ch, ldc, bias, resid, ldr, scale, gmul);
            __syncwarp();
        }
    }
}

// ---------------------------------------------------------------------------
// Fused flash attention (R10)
// ---------------------------------------------------------------------------
#define FA_SMEM 109056
#define FA_OFF_K 18432
#define FA_OFF_V 36864
#define FA_OFF_SF 55296
#define FA_OFF_PH 90112
#define FA_OFF_L 108544

__global__ __launch_bounds__(128, 2)
void flash_attn(const __half* __restrict__ qkv, __half* __restrict__ O)
{
    extern __shared__ __half smh[];
    const uint32_t sb = smem_u32(smh);
    char* smc = (char*)smh;

    const int tid = threadIdx.x;
    const int wid = tid >> 5, lid = tid & 31;
    const int qb = blockIdx.x;
    const int bh = blockIdx.y;
    const int zb = bh / 12, zh = bh % 12;

    const long long TQ = 1024LL * 2304LL;
    const __half* qbase = qkv + (long long)zb * TQ + zh * 64 + (long long)(qb * 128) * 2304;
    const __half* kbase = qkv + 768  + (long long)zb * TQ + zh * 64;
    const __half* vbase = qkv + 1536 + (long long)zb * TQ + zh * 64;

    #pragma unroll
    for (int q = 0; q < 8; q++) {
        const int id = q * 128 + tid;
        const int row = id >> 3, c16 = id & 7;
        cp_async16(sb + (uint32_t)(row * 144 + c16 * 16),
                   qbase + (long long)row * 2304 + c16 * 8, 16);
    }
    auto stageKV = [&](int it, int buf) {
        const long long r0 = (long long)(it * 64);
        const uint32_t offK = FA_OFF_K + (uint32_t)buf * 9216;
        const uint32_t offV = FA_OFF_V + (uint32_t)buf * 9216;
        #pragma unroll
        for (int q = 0; q < 4; q++) {
            const int id = q * 128 + tid;
            const int row = id >> 3, c16 = id & 7;
            const uint32_t so = (uint32_t)(row * 144 + c16 * 16);
            cp_async16(sb + offK + so, kbase + (r0 + row) * 2304 + c16 * 8, 16);
            cp_async16(sb + offV + so, vbase + (r0 + row) * 2304 + c16 * 8, 16);
        }
    };
    stageKV(0, 0);
    cp_commit();

    wmma::fragment<wmma::accumulator, 16, 16, 16, float> o_acc[2][4];
    #pragma unroll
    for (int i = 0; i < 2; i++)
        #pragma unroll
        for (int j = 0; j < 4; j++) wmma::fill_fragment(o_acc[i][j], 0.0f);
    float l = 0.0f;

    const __half* Qw = smh + (wid * 32) * TLDH;
    float* Sf = (float*)(smc + FA_OFF_SF) + wid * (32 * 68);
    __half* Ph = (__half*)(smc + FA_OFF_PH) + wid * (32 * TLDH);

    for (int it = 0; it < 16; it++) {
        if (it + 1 < 16) {
            stageKV(it + 1, (it + 1) & 1);
            cp_commit();
            cp_wait<1>();
        } else {
            cp_wait<0>();
        }
        __syncthreads();

        const __half* Ks = (const __half*)(smc + FA_OFF_K + (it & 1) * 9216);
        const __half* Vs = (const __half*)(smc + FA_OFF_V + (it & 1) * 9216);

        wmma::fragment<wmma::accumulator, 16, 16, 16, float> sa[2][4];
        #pragma unroll
        for (int i = 0; i < 2; i++)
            #pragma unroll
            for (int j = 0; j < 4; j++) wmma::fill_fragment(sa[i][j], 0.0f);
        #pragma unroll
        for (int kk = 0; kk < 4; kk++) {
            wmma::fragment<wmma::matrix_a, 16, 16, 16, __half, wmma::row_major> aq[2];
            wmma::load_matrix_sync(aq[0], Qw + kk * 16, TLDH);
            wmma::load_matrix_sync(aq[1], Qw + 16 * TLDH + kk * 16, TLDH);
            #pragma unroll
            for (int j = 0; j < 4; j++) {
                wmma::fragment<wmma::matrix_b, 16, 16, 16, __half, wmma::col_major> bk;
                wmma::load_matrix_sync(bk, Ks + (j * 16) * TLDH + kk * 16, TLDH);
                wmma::mma_sync(sa[0][j], aq[0], bk, sa[0][j]);
                wmma::mma_sync(sa[1][j], aq[1], bk, sa[1][j]);
            }
        }
        #pragma unroll
        for (int i = 0; i < 2; i++)
            #pragma unroll
            for (int j = 0; j < 4; j++) {
                #pragma unroll
                for (int e = 0; e < 8; e++)
                    sa[i][j].x[e] = __expf(sa[i][j].x[e] * 0.125f);
                wmma::store_matrix_sync(Sf + (i * 16) * 68 + j * 16, sa[i][j], 68,
                                        wmma::mem_row_major);
            }
        __syncwarp();
        {
            const float* srow = Sf + lid * 68;
            __half* prow = Ph + lid * TLDH;
            float sum = 0.0f;
            #pragma unroll
            for (int c = 0; c < 64; c += 4) {
                float4 v = *(const float4*)(srow + c);
                sum += (v.x + v.y) + (v.z + v.w);
                *(__half2*)(prow + c)     = __floats2half2_rn(v.x, v.y);
                *(__half2*)(prow + c + 2) = __floats2half2_rn(v.z, v.w);
            }
            l += sum;
        }
        __syncwarp();
        #pragma unroll
        for (int kk = 0; kk < 4; kk++) {
            wmma::fragment<wmma::matrix_a, 16, 16, 16, __half, wmma::row_major> ap[2];
            wmma::load_matrix_sync(ap[0], Ph + kk * 16, TLDH);
            wmma::load_matrix_sync(ap[1], Ph + 16 * TLDH + kk * 16, TLDH);
            #pragma unroll
            for (int j = 0; j < 4; j++) {
                wmma::fragment<wmma::matrix_b, 16, 16, 16, __half, wmma::row_major> bv;
                wmma::load_matrix_sync(bv, Vs + (kk * 16) * TLDH + j * 16, TLDH);
                wmma::mma_sync(o_acc[0][j], ap[0], bv, o_acc[0][j]);
                wmma::mma_sync(o_acc[1][j], ap[1], bv, o_acc[1][j]);
            }
        }
        __syncthreads();
    }

    float* l_sm = (float*)(smc + FA_OFF_L);
    l_sm[wid * 32 + lid] = l;
    __syncwarp();

    float* patch = Sf;
    const long long orow0 = (long long)zb * 1024 + qb * 128 + wid * 32;
    #pragma unroll
    for (int i = 0; i < 2; i++) {
        #pragma unroll
        for (int j = 0; j < 4; j++) {
            wmma::store_matrix_sync(patch, o_acc[i][j], 16, wmma::mem_row_major);
            __syncwarp();
            #pragma unroll
            for (int q = 0; q < 2; q++) {
                const int idx = lid + 32 * q;
                const int r = idx >> 2, c4 = idx & 3;
                float4 v = *(const float4*)(patch + r * 16 + c4 * 4);
                const float linv = 1.0f / l_sm[wid * 32 + i * 16 + r];
                __half2 h0 = __floats2half2_rn(v.x * linv, v.y * linv);
                __half2 h1 = __floats2half2_rn(v.z * linv, v.w * linv);
                uint2 pk;
                pk.x = *(uint32_t*)&h0; pk.y = *(uint32_t*)&h1;
                const long long m = orow0 + i * 16 + r;
                const int n = zh * 64 + j * 16 + c4 * 4;
                *(uint2*)(O + m * 768 + n) = pk;
            }
            __syncwarp();
        }
    }
}

// ---------------------------------------------------------------------------
// preps / LN / conv / scan
// ---------------------------------------------------------------------------
__global__ __launch_bounds__(256)
void transpose_f2h(const float* __restrict__ in, int ldi,
                   __half* __restrict__ out, int ldo, int R, int C)
{
    __shared__ float t[32][33];
    const int r0 = blockIdx.y * 32, c0 = blockIdx.x * 32;
    const int tx = threadIdx.x & 31, ty = threadIdx.x >> 5;
    #pragma unroll
    for (int i = 0; i < 32; i += 8) {
        const int r = r0 + ty + i, c = c0 + tx;
        t[ty + i][tx] = (r < R && c < C) ? in[(long long)r * ldi + c] : 0.f;
    }
    __syncthreads();
    #pragma unroll
    for (int i = 0; i < 32; i += 8) {
        const int r = c0 + ty + i, c = r0 + tx;
        if (r < C && c < R) out[(long long)r * ldo + c] = __float2half_rn(t[tx][ty + i]);
    }
}

__global__ __launch_bounds__(256)
void cast_f2h(const float* __restrict__ in, __half* __restrict__ out, int n)
{
    int i = blockIdx.x * 256 + threadIdx.x;
    if (i < n) out[i] = __float2half_rn(in[i]);
}

__global__ __launch_bounds__(256)
void dtw_prep(const float* __restrict__ dtw, __half* __restrict__ out)
{
    int i = blockIdx.x * 256 + threadIdx.x;
    int n = i >> 6, k = i & 63;
    out[i] = (k < 48) ? __float2half_rn(dtw[k * 1536 + n]) : __half(0.f);
}

// sum 4 K-split partials -> final float dbl [8192,80]; also emit half dblh
// [8192,64] (cols 0..47 = dbl, 48..63 = 0)
__global__ __launch_bounds__(256)
void dbl_sum(const float* __restrict__ part, float* __restrict__ dbl,
             __half* __restrict__ dblh)
{
    int i = blockIdx.x * 256 + threadIdx.x;   // < 8192*80
    if (i >= 8192 * 80) return;
    const long long S = 8192LL * 80LL;
    float s = part[i] + part[S + i] + part[2 * S + i] + part[3 * S + i];
    dbl[i] = s;
    int r = i / 80, c = i % 80;
    if (c < 48)      dblh[r * 64 + c] = __float2half_rn(s);
    else if (c < 64) dblh[r * 64 + c] = __half(0.f);
}

__global__ __launch_bounds__(256)
void ln_kernel(const float* __restrict__ x, const float* __restrict__ g,
               const float* __restrict__ b, __half* __restrict__ y)
{
    long long row = blockIdx.x;
    const float* xr = x + row * 768;
    __half* yr = y + row * 768;
    int tid = threadIdx.x;

    float v0 = xr[tid], v1 = xr[tid + 256], v2 = xr[tid + 512];
    float s  = v0 + v1 + v2;
    float ss = v0 * v0 + v1 * v1 + v2 * v2;

    #pragma unroll
    for (int o = 16; o; o >>= 1) {
        s  += __shfl_xor_sync(0xffffffffu, s, o);
        ss += __shfl_xor_sync(0xffffffffu, ss, o);
    }
    __shared__ float sh_s[8], sh_ss[8];
    int w = tid >> 5, l = tid & 31;
    if (l == 0) { sh_s[w] = s; sh_ss[w] = ss; }
    __syncthreads();
    if (w == 0) {
        float s2  = (l < 8) ? sh_s[l]  : 0.f;
        float ss2 = (l < 8) ? sh_ss[l] : 0.f;
        #pragma unroll
        for (int o = 4; o; o >>= 1) {
            s2  += __shfl_xor_sync(0xffffffffu, s2, o);
            ss2 += __shfl_xor_sync(0xffffffffu, ss2, o);
        }
        if (l == 0) { sh_s[0] = s2; sh_ss[0] = ss2; }
    }
    __syncthreads();
    float mean = sh_s[0] * (1.0f / 768.0f);
    float var  = sh_ss[0] * (1.0f / 768.0f) - mean * mean;
    float rstd = rsqrtf(var + 1e-5f);

    yr[tid]       = __float2half_rn((v0 - mean) * rstd * g[tid]       + b[tid]);
    yr[tid + 256] = __float2half_rn((v1 - mean) * rstd * g[tid + 256] + b[tid + 256]);
    yr[tid + 512] = __float2half_rn((v2 - mean) * rstd * g[tid + 512] + b[tid + 512]);
}

// conv over half xz; scalar 1 channel/thread (measured best layout)
__global__ __launch_bounds__(256)
void conv_silu_kernel(const __half* __restrict__ xz, const float* __restrict__ cw,
                      const float* __restrict__ cb, __half* __restrict__ uh)
{
    int idx = blockIdx.x * 256 + threadIdx.x;
    int d   = idx % 1536;
    int tok = idx / 1536;
    int t   = tok & 1023;
    float acc = cb[d];
    const __half* base = xz + (long long)tok * 3072 + d;
    #pragma unroll
    for (int j = 0; j < 4; j++) {
        int tt = t - 3 + j;
        if (tt >= 0)
            acc = fmaf(__half2float(base[(long long)(j - 3) * 3072]), cw[d * 4 + j], acc);
    }
    uh[(long long)tok * 1536 + d] = __float2half_rn(silu_f(acc));
}

// scan over half u / half xz-res
__global__ __launch_bounds__(256)
void scan_kernel(const float* __restrict__ dt, const float* __restrict__ dbl,
                 const __half* __restrict__ u, const __half* __restrict__ xz,
                 const float* __restrict__ Alog, const float* __restrict__ Dp,
                 __half* __restrict__ y)
{
    int gg = blockIdx.x * 16 + (threadIdx.x >> 4);
    int s  = threadIdx.x & 15;
    int d  = gg % 1536, b = gg / 1536;

    float A  = -expf(Alog[d * 16 + s]);
    float Dv = Dp[d];
    float h  = 0.0f;
    long long tokbase = (long long)b * 1024;

    for (int t = 0; t < 1024; t++) {
        long long tok = tokbase + t;
        float dtv = dt[tok * 1536 + d];
        float uv  = __half2float(u[tok * 1536 + d]);
        float Bv  = dbl[tok * 80 + 48 + s];
        float Cv  = dbl[tok * 80 + 64 + s];
        float dA  = __expf(dtv * A);
        h = fmaf(dA, h, dtv * Bv * uv);
        float part = h * Cv;
        part += __shfl_xor_sync(0xffffffffu, part, 8, 16);
        part += __shfl_xor_sync(0xffffffffu, part, 4, 16);
        part += __shfl_xor_sync(0xffffffffu, part, 2, 16);
        part += __shfl_xor_sync(0xffffffffu, part, 1, 16);
        if (s == 0) {
            float rv = __half2float(xz[tok * 3072 + 1536 + d]);
            y[tok * 1536 + d] = __float2half_rn((part + uv * Dv) * silu_f(rv));
        }
    }
}

// ---------------------------------------------------------------------------
// Host orchestration
// ---------------------------------------------------------------------------
extern "C" void kernel_launch(void* const* d_in, const int* in_sizes, int n_in,
                              void* d_out, int out_size)
{
    const float* x    = (const float*)d_in[0];
    const float* n1g  = (const float*)d_in[1];
    const float* n1b  = (const float*)d_in[2];
    const float* aiw  = (const float*)d_in[3];
    const float* aib  = (const float*)d_in[4];
    const float* aow  = (const float*)d_in[5];
    const float* aob  = (const float*)d_in[6];
    const float* n2g  = (const float*)d_in[7];
    const float* n2b  = (const float*)d_in[8];
    const float* w1   = (const float*)d_in[9];
    const float* b1   = (const float*)d_in[10];
    const float* w2   = (const float*)d_in[11];
    const float* b2   = (const float*)d_in[12];
    const float* n3g  = (const float*)d_in[13];
    const float* n3b  = (const float*)d_in[14];
    const float* minw = (const float*)d_in[15];
    const float* cw   = (const float*)d_in[16];
    const float* cb   = (const float*)d_in[17];
    const float* xpw  = (const float*)d_in[18];
    const float* dtw  = (const float*)d_in[19];
    const float* dtbi = (const float*)d_in[20];
    const float* alog = (const float*)d_in[21];
    const float* dpar = (const float*)d_in[22];
    const float* mow  = (const float*)d_in[23];
    const float* gate = (const float*)d_in[24];
    float* out = (float*)d_out;

    __half *lnh, *qkvh, *attnh, *hh, *uh, *dblh, *yh, *wth;
    float  *dbl, *gdt;
    cudaGetSymbolAddress((void**)&lnh,   g_lnh);
    cudaGetSymbolAddress((void**)&qkvh,  g_qkvh);
    cudaGetSymbolAddress((void**)&attnh, g_attnh);
    cudaGetSymbolAddress((void**)&hh,    g_hh);
    cudaGetSymbolAddress((void**)&uh,    g_uh);
    cudaGetSymbolAddress((void**)&dbl,   g_dbl);
    cudaGetSymbolAddress((void**)&dblh,  g_dblh);
    cudaGetSymbolAddress((void**)&gdt,   g_dt);
    cudaGetSymbolAddress((void**)&yh,    g_yh);
    cudaGetSymbolAddress((void**)&wth,   g_wth);

    cudaFuncSetAttribute(tgemm<0, true>,  cudaFuncAttributeMaxDynamicSharedMemorySize, TG_SMEM);
    cudaFuncSetAttribute(tgemm<0, false>, cudaFuncAttributeMaxDynamicSharedMemorySize, TG_SMEM);
    cudaFuncSetAttribute(tgemm<1, true>,  cudaFuncAttributeMaxDynamicSharedMemorySize, TG_SMEM);
    cudaFuncSetAttribute(tgemm<2, false>, cudaFuncAttributeMaxDynamicSharedMemorySize, TG_SMEM);
    cudaFuncSetAttribute(tgemm<3, true>,  cudaFuncAttributeMaxDynamicSharedMemorySize, TG_SMEM);
    cudaFuncSetAttribute(tgemm<4, false>, cudaFuncAttributeMaxDynamicSharedMemorySize, TG_SMEM);
    cudaFuncSetAttribute(tgemm<5, false>, cudaFuncAttributeMaxDynamicSharedMemorySize, TG_SMEM);
    cudaFuncSetAttribute(flash_attn,      cudaFuncAttributeMaxDynamicSharedMemorySize, FA_SMEM);

    // launch order: 0 cast_aiw, 1 cast_aow, 2 ln1, 3 QKV gemm, 4 flash, 5 outproj
    cast_f2h<<<(2304 * 768 + 255) / 256, 256>>>(aiw, wth + WH_AIW, 2304 * 768);   // 0
    cast_f2h<<<(768 * 768 + 255) / 256, 256>>>(aow, wth + WH_AOW, 768 * 768);     // 1
    ln_kernel<<<8192, 256>>>(x, n1g, n1b, lnh);                                   // 2

    // 3) QKV = LN1 @ attn_in_w^T + b
    tgemm<1, true><<<dim3(18, 64, 1), 128, TG_SMEM>>>(
        lnh, 768, wth + WH_AIW, 768, qkvh, 2304,
        8192, 2304, 768, aib, nullptr, 0, 1.0f, nullptr, 0, 0);

    // 4) fused attention
    flash_attn<<<dim3(8, 96), 128, FA_SMEM>>>(qkvh, attnh);

    // 5) x = x_in + O @ attn_out_w^T + b
    tgemm<2, false><<<dim3(6, 64, 1), 128, TG_SMEM>>>(
        attnh, 768, wth + WH_AOW, 768, out, 768,
        8192, 768, 768, aob, x, 768, 1.0f, nullptr, 0, 0);

    // remaining weight preps
    transpose_f2h<<<dim3(96, 24, 1), 256>>>(w1, 3072, wth + WH_W1, 768, 768, 3072);
    transpose_f2h<<<dim3(24, 96, 1), 256>>>(w2, 768, wth + WH_W2, 3072, 3072, 768);
    transpose_f2h<<<dim3(96, 24, 1), 256>>>(minw, 3072, wth + WH_MIN, 768, 768, 3072);
    transpose_f2h<<<dim3(24, 48, 1), 256>>>(mow, 768, wth + WH_MOW, 1536, 1536, 768);
    transpose_f2h<<<dim3(3, 48, 1), 256>>>(xpw, 80, wth + WH_XPW, 1536, 1536, 80);
    dtw_prep<<<(1536 * 64 + 255) / 256, 256>>>(dtw, wth + WH_DTW);

    // LN2
    ln_kernel<<<8192, 256>>>(out, n2g, n2b, lnh);

    // H = gelu(LN2 @ W1 + b1) -> half
    tgemm<3, true><<<dim3(24, 64, 1), 128, TG_SMEM>>>(
        lnh, 768, wth + WH_W1, 768, hh, 3072,
        8192, 3072, 768, b1, nullptr, 0, 1.0f, nullptr, 0, 0);

    // x += H @ W2 + b2
    tgemm<2, false><<<dim3(6, 64, 1), 128, TG_SMEM>>>(
        hh, 3072, wth + WH_W2, 3072, out, 768,
        8192, 768, 3072, b2, out, 768, 1.0f, nullptr, 0, 0);

    // LN3
    ln_kernel<<<8192, 256>>>(out, n3g, n3b, lnh);

    // xz = LN3 @ m_in_w -> half (reuses hh)
    tgemm<0, true><<<dim3(24, 64, 1), 128, TG_SMEM>>>(
        lnh, 768, wth + WH_MIN, 768, hh, 3072,
        8192, 3072, 768, nullptr, nullptr, 0, 1.0f, nullptr, 0, 0);

    // u = silu(conv(xz[:, :1536]) + cb) -> half
    conv_silu_kernel<<<49152, 256>>>(hh, cw, cb, uh);

    // dbl partials = u @ xproj_w, K split x4 (K=1536 -> 4x384), partials in gdt
    tgemm<0, false><<<dim3(1, 64, 4), 128, TG_SMEM>>>(
        uh, 1536, wth + WH_XPW, 1536, gdt, 80,
        8192, 80, 384, nullptr, nullptr, 0, 1.0f, nullptr,
        384, 8192LL * 80LL);

    // sum partials -> dbl (float) + dblh (half padded)
    dbl_sum<<<(8192 * 80 + 255) / 256, 256>>>(gdt, dbl, dblh);

    // dt = softplus(dbl48 @ dt_w + dt_b) -> float (overwrites gdt)
    tgemm<4, false><<<dim3(12, 64, 1), 128, TG_SMEM>>>(
        dblh, 64, wth + WH_DTW, 64, gdt, 1536,
        8192, 1536, 64, dtbi, nullptr, 0, 1.0f, nullptr, 0, 0);

    // selective scan + (u*D) + *silu(res) -> half
    scan_kernel<<<768, 256>>>(gdt, dbl, uh, hh, alog, dpar, yh);

    // out = x + sigmoid(gate) * (y @ m_out_w)
    tgemm<5, false><<<dim3(6, 64, 1), 128, TG_SMEM>>>(
        yh, 1536, wth + WH_MOW, 1536, out, 768,
        8192, 768, 1536, nullptr, out, 768, 1.0f, gate, 0, 0);
}

// round 15
// speedup vs baseline: 1.1176x; 1.0078x over previous
#include <cuda_runtime.h>
#include <cuda_fp16.h>
#include <mma.h>
#include <cstdint>
#include <math.h>

using namespace nvcuda;

// ---------------------------------------------------------------------------
// MambaViTBlock: B=8, N=1024 (TOK=8192), D=768, NH=12 (dh=64), MLPH=3072,
//                DI=1536, DS=16, DTR=48, K=4
// Round 15: exact R10 configuration (measured best 1903us) + dbl_prep fused
// into the xproj GEMM epilogue (EPI 6: dual float+padded-half output).
// ---------------------------------------------------------------------------

__device__ __half g_lnh  [8192u * 768u];
__device__ __half g_qkvh [8192u * 2304u];
__device__ __half g_attnh[8192u * 768u];
__device__ __half g_hh   [8192u * 3072u];   // MLP hidden, then mamba xz (half)
__device__ __half g_uh   [8192u * 1536u];
__device__ float  g_dbl  [8192u * 80u];     // xproj out (dt_raw | B | C)
__device__ __half g_dblh [8192u * 64u];     // dbl[:, :48] padded to 64 (half)
__device__ float  g_dt   [8192u * 1536u];
__device__ __half g_yh   [8192u * 1536u];
__device__ __half g_wth  [10838016u];

#define WH_AIW  0u
#define WH_AOW  1769472u
#define WH_W1   2359296u
#define WH_W2   4718592u
#define WH_MIN  7077888u
#define WH_MOW  9437184u
#define WH_XPW  10616832u
#define WH_DTW  10739712u

__device__ __forceinline__ float gelu_exact(float v) {
    return 0.5f * v * (1.0f + erff(v * 0.7071067811865475f));
}
__device__ __forceinline__ float softplus_f(float v) {
    return fmaxf(v, 0.0f) + log1pf(expf(-fabsf(v)));
}
__device__ __forceinline__ float silu_f(float v) {
    return v / (1.0f + __expf(-v));
}

__device__ __forceinline__ uint32_t smem_u32(const void* p) {
    uint32_t a;
    asm("{ .reg .u64 t; cvta.to.shared.u64 t, %1; cvt.u32.u64 %0, t; }" : "=r"(a) : "l"(p));
    return a;
}
__device__ __forceinline__ void cp_async16(uint32_t dst, const void* src, int sz) {
    asm volatile("cp.async.ca.shared.global [%0], [%1], 16, %2;"
                 :: "r"(dst), "l"(src), "r"(sz));
}
__device__ __forceinline__ void cp_commit() { asm volatile("cp.async.commit_group;"); }
template<int N>
__device__ __forceinline__ void cp_wait() {
    asm volatile("cp.async.wait_group %0;" :: "n"(N));
}

#define TLDH 72

// ---------------------------------------------------------------------------
// Shared epilogue helper (per 16x16 patch; patch stride 16 floats)
// EPI: 0 none, 1 +bias, 2 +bias+resid, 3 gelu(+bias), 4 softplus(+bias),
//      5 resid + sigmoid(gate)*acc, 6 float out + padded-half aux out
// ---------------------------------------------------------------------------
template<int EPI, bool OH>
__device__ __forceinline__ void epi_patch(
    const float* patch, int lid, int mbase, int nfrag,
    float* Cf, __half* Ch, int ldc,
    const float* bias, const float* resid, int ldr,
    float scale, float gmul, __half* aux)
{
    #pragma unroll
    for (int q = 0; q < 2; q++) {
        const int idx = lid + 32 * q;
        const int r = idx >> 2, c4 = idx & 3;
        float4 v4 = *(const float4*)(patch + r * 16 + c4 * 4);
        const int n = nfrag + c4 * 4;
        const int m = mbase + r;
        float vv[4] = {v4.x, v4.y, v4.z, v4.w};
        #pragma unroll
        for (int qq = 0; qq < 4; qq++) {
            float t = vv[qq] * scale;
            if (EPI >= 1 && EPI <= 4) t += bias[n + qq];
            if (EPI == 3) t = gelu_exact(t);
            if (EPI == 4) t = softplus_f(t);
            if (EPI == 2) t += resid[(long long)m * ldr + n + qq];
            if (EPI == 5) t = resid[(long long)m * ldr + n + qq] + gmul * t;
            vv[qq] = t;
        }
        if (OH) {
            __half2 h0 = __floats2half2_rn(vv[0], vv[1]);
            __half2 h1 = __floats2half2_rn(vv[2], vv[3]);
            uint2 pk;
            pk.x = *(uint32_t*)&h0; pk.y = *(uint32_t*)&h1;
            *(uint2*)(Ch + (long long)m * ldc + n) = pk;
        } else {
            *(float4*)(Cf + (long long)m * ldc + n) =
                make_float4(vv[0], vv[1], vv[2], vv[3]);
        }
        if (EPI == 6) {
            // aux: [m, 64] half, cols 0..47 = value, 48..63 = 0
            #pragma unroll
            for (int qq = 0; qq < 4; qq++) {
                const int nn = n + qq;
                if (nn < 48)      aux[(long long)m * 64 + nn] = __float2half_rn(vv[qq]);
                else if (nn < 64) aux[(long long)m * 64 + nn] = __half(0.f);
            }
        }
    }
}

// ---------------------------------------------------------------------------
// tgemm: 128x128 tile, 128 threads (4 warps of 64x64), BK=64, 2-stage.
// launch_bounds(128,2): 256-reg budget -> ptxas fragment prefetching.
// (R10 structure — measured best.)
// ---------------------------------------------------------------------------
#define TG_SMEM (2 * 2 * 128 * TLDH * 2)   // 73728 B

template<int EPI, bool OH>
__global__ __launch_bounds__(128, 2)
void tgemm(const __half* __restrict__ A, int lda,
           const __half* __restrict__ B, int ldb,
           void* __restrict__ Cv, int ldc,
           int M, int N, int K,
           const float* __restrict__ bias,
           const float* __restrict__ resid, int ldr,
           float scale, const float* __restrict__ gatep,
           __half* __restrict__ aux)
{
    extern __shared__ __half smh[];
    const uint32_t sb = smem_u32(smh);

    const int tid = threadIdx.x;
    const int wid = tid >> 5, lid = tid & 31;
    const int warpM = wid & 1;
    const int warpN = wid >> 1;

    float*  Cf = (float*)Cv;
    __half* Ch = (__half*)Cv;

    const int m0 = blockIdx.y * 128, n0 = blockIdx.x * 128;
    const int NC = K / 64;

    wmma::fragment<wmma::accumulator, 16, 16, 16, float> acc[4][4];
    #pragma unroll
    for (int i = 0; i < 4; i++)
        #pragma unroll
        for (int j = 0; j < 4; j++) wmma::fill_fragment(acc[i][j], 0.0f);

    auto stage = [&](int c, int buf) {
        const int k0 = c * 64;
        const uint32_t offA = (uint32_t)buf * (2 * 128 * TLDH) * 2;
        const uint32_t offB = offA + (128 * TLDH) * 2;
        #pragma unroll
        for (int q = 0; q < 8; q++) {
            const int id  = q * 128 + tid;
            const int row = id >> 3, c16 = id & 7;
            const uint32_t so = (uint32_t)(row * (TLDH * 2) + c16 * 16);
            cp_async16(sb + offA + so,
                       A + (long long)(m0 + row) * lda + k0 + c16 * 8, 16);
            const bool bv = (n0 + row) < N;
            const __half* bsrc = bv ? (B + (long long)(n0 + row) * ldb + k0 + c16 * 8) : B;
            cp_async16(sb + offB + so, bsrc, bv ? 16 : 0);
        }
    };

    auto compute = [&](int buf) {
        const __half* Asb = smh + buf * (2 * 128 * TLDH);
        const __half* Bsb = Asb + 128 * TLDH;
        #pragma unroll
        for (int kk = 0; kk < 64; kk += 16) {
            wmma::fragment<wmma::matrix_a, 16, 16, 16, __half, wmma::row_major> af[4];
            #pragma unroll
            for (int i = 0; i < 4; i++)
                wmma::load_matrix_sync(af[i], Asb + (warpM * 64 + i * 16) * TLDH + kk, TLDH);
            wmma::fragment<wmma::matrix_b, 16, 16, 16, __half, wmma::col_major> bf[2];
            wmma::load_matrix_sync(bf[0], Bsb + (warpN * 64) * TLDH + kk, TLDH);
            #pragma unroll
            for (int j = 0; j < 4; j++) {
                if (j < 3)
                    wmma::load_matrix_sync(bf[(j + 1) & 1],
                        Bsb + (warpN * 64 + (j + 1) * 16) * TLDH + kk, TLDH);
                #pragma unroll
                for (int i = 0; i < 4; i++)
                    wmma::mma_sync(acc[i][j], af[i], bf[j & 1], acc[i][j]);
            }
        }
    };

    stage(0, 0);
    cp_commit();

    for (int c = 0; c < NC; c++) {
        if (c + 1 < NC) {
            stage(c + 1, (c + 1) & 1);
            cp_commit();
            cp_wait<1>();
        } else {
            cp_wait<0>();
        }
        __syncthreads();
        compute(c & 1);
        __syncthreads();
    }

    float gmul = 1.0f;
    if (EPI == 5) gmul = 1.0f / (1.0f + __expf(-gatep[0]));
    float* patch = (float*)smh + wid * 256;

    #pragma unroll
    for (int i = 0; i < 4; i++) {
        #pragma unroll
        for (int j = 0; j < 4; j++) {
            const int nfrag = n0 + warpN * 64 + j * 16;
            if (nfrag >= N) continue;
            wmma::store_matrix_sync(patch, acc[i][j], 16, wmma::mem_row_major);
            __syncwarp();
            epi_patch<EPI, OH>(patch, lid, m0 + warpM * 64 + i * 16, nfrag,
                               Cf, Ch, ldc, bias, resid, ldr, scale, gmul, aux);
            __syncwarp();
        }
    }
}

// ---------------------------------------------------------------------------
// Fused flash attention (R10)
// ---------------------------------------------------------------------------
#define FA_SMEM 109056
#define FA_OFF_K 18432
#define FA_OFF_V 36864
#define FA_OFF_SF 55296
#define FA_OFF_PH 90112
#define FA_OFF_L 108544

__global__ __launch_bounds__(128, 2)
void flash_attn(const __half* __restrict__ qkv, __half* __restrict__ O)
{
    extern __shared__ __half smh[];
    const uint32_t sb = smem_u32(smh);
    char* smc = (char*)smh;

    const int tid = threadIdx.x;
    const int wid = tid >> 5, lid = tid & 31;
    const int qb = blockIdx.x;
    const int bh = blockIdx.y;
    const int zb = bh / 12, zh = bh % 12;

    const long long TQ = 1024LL * 2304LL;
    const __half* qbase = qkv + (long long)zb * TQ + zh * 64 + (long long)(qb * 128) * 2304;
    const __half* kbase = qkv + 768  + (long long)zb * TQ + zh * 64;
    const __half* vbase = qkv + 1536 + (long long)zb * TQ + zh * 64;

    #pragma unroll
    for (int q = 0; q < 8; q++) {
        const int id = q * 128 + tid;
        const int row = id >> 3, c16 = id & 7;
        cp_async16(sb + (uint32_t)(row * 144 + c16 * 16),
                   qbase + (long long)row * 2304 + c16 * 8, 16);
    }
    auto stageKV = [&](int it, int buf) {
        const long long r0 = (long long)(it * 64);
        const uint32_t offK = FA_OFF_K + (uint32_t)buf * 9216;
        const uint32_t offV = FA_OFF_V + (uint32_t)buf * 9216;
        #pragma unroll
        for (int q = 0; q < 4; q++) {
            const int id = q * 128 + tid;
            const int row = id >> 3, c16 = id & 7;
            const uint32_t so = (uint32_t)(row * 144 + c16 * 16);
            cp_async16(sb + offK + so, kbase + (r0 + row) * 2304 + c16 * 8, 16);
            cp_async16(sb + offV + so, vbase + (r0 + row) * 2304 + c16 * 8, 16);
        }
    };
    stageKV(0, 0);
    cp_commit();

    wmma::fragment<wmma::accumulator, 16, 16, 16, float> o_acc[2][4];
    #pragma unroll
    for (int i = 0; i < 2; i++)
        #pragma unroll
        for (int j = 0; j < 4; j++) wmma::fill_fragment(o_acc[i][j], 0.0f);
    float l = 0.0f;

    const __half* Qw = smh + (wid * 32) * TLDH;
    float* Sf = (float*)(smc + FA_OFF_SF) + wid * (32 * 68);
    __half* Ph = (__half*)(smc + FA_OFF_PH) + wid * (32 * TLDH);

    for (int it = 0; it < 16; it++) {
        if (it + 1 < 16) {
            stageKV(it + 1, (it + 1) & 1);
            cp_commit();
            cp_wait<1>();
        } else {
            cp_wait<0>();
        }
        __syncthreads();

        const __half* Ks = (const __half*)(smc + FA_OFF_K + (it & 1) * 9216);
        const __half* Vs = (const __half*)(smc + FA_OFF_V + (it & 1) * 9216);

        wmma::fragment<wmma::accumulator, 16, 16, 16, float> sa[2][4];
        #pragma unroll
        for (int i = 0; i < 2; i++)
            #pragma unroll
            for (int j = 0; j < 4; j++) wmma::fill_fragment(sa[i][j], 0.0f);
        #pragma unroll
        for (int kk = 0; kk < 4; kk++) {
            wmma::fragment<wmma::matrix_a, 16, 16, 16, __half, wmma::row_major> aq[2];
            wmma::load_matrix_sync(aq[0], Qw + kk * 16, TLDH);
            wmma::load_matrix_sync(aq[1], Qw + 16 * TLDH + kk * 16, TLDH);
            #pragma unroll
            for (int j = 0; j < 4; j++) {
                wmma::fragment<wmma::matrix_b, 16, 16, 16, __half, wmma::col_major> bk;
                wmma::load_matrix_sync(bk, Ks + (j * 16) * TLDH + kk * 16, TLDH);
                wmma::mma_sync(sa[0][j], aq[0], bk, sa[0][j]);
                wmma::mma_sync(sa[1][j], aq[1], bk, sa[1][j]);
            }
        }
        #pragma unroll
        for (int i = 0; i < 2; i++)
            #pragma unroll
            for (int j = 0; j < 4; j++) {
                #pragma unroll
                for (int e = 0; e < 8; e++)
                    sa[i][j].x[e] = __expf(sa[i][j].x[e] * 0.125f);
                wmma::store_matrix_sync(Sf + (i * 16) * 68 + j * 16, sa[i][j], 68,
                                        wmma::mem_row_major);
            }
        __syncwarp();
        {
            const float* srow = Sf + lid * 68;
            __half* prow = Ph + lid * TLDH;
            float sum = 0.0f;
            #pragma unroll
            for (int c = 0; c < 64; c += 4) {
                float4 v = *(const float4*)(srow + c);
                sum += (v.x + v.y) + (v.z + v.w);
                *(__half2*)(prow + c)     = __floats2half2_rn(v.x, v.y);
                *(__half2*)(prow + c + 2) = __floats2half2_rn(v.z, v.w);
            }
            l += sum;
        }
        __syncwarp();
        #pragma unroll
        for (int kk = 0; kk < 4; kk++) {
            wmma::fragment<wmma::matrix_a, 16, 16, 16, __half, wmma::row_major> ap[2];
            wmma::load_matrix_sync(ap[0], Ph + kk * 16, TLDH);
            wmma::load_matrix_sync(ap[1], Ph + 16 * TLDH + kk * 16, TLDH);
            #pragma unroll
            for (int j = 0; j < 4; j++) {
                wmma::fragment<wmma::matrix_b, 16, 16, 16, __half, wmma::row_major> bv;
                wmma::load_matrix_sync(bv, Vs + (kk * 16) * TLDH + j * 16, TLDH);
                wmma::mma_sync(o_acc[0][j], ap[0], bv, o_acc[0][j]);
                wmma::mma_sync(o_acc[1][j], ap[1], bv, o_acc[1][j]);
            }
        }
        __syncthreads();
    }

    float* l_sm = (float*)(smc + FA_OFF_L);
    l_sm[wid * 32 + lid] = l;
    __syncwarp();

    float* patch = Sf;
    const long long orow0 = (long long)zb * 1024 + qb * 128 + wid * 32;
    #pragma unroll
    for (int i = 0; i < 2; i++) {
        #pragma unroll
        for (int j = 0; j < 4; j++) {
            wmma::store_matrix_sync(patch, o_acc[i][j], 16, wmma::mem_row_major);
            __syncwarp();
            #pragma unroll
            for (int q = 0; q < 2; q++) {
                const int idx = lid + 32 * q;
                const int r = idx >> 2, c4 = idx & 3;
                float4 v = *(const float4*)(patch + r * 16 + c4 * 4);
                const float linv = 1.0f / l_sm[wid * 32 + i * 16 + r];
                __half2 h0 = __floats2half2_rn(v.x * linv, v.y * linv);
                __half2 h1 = __floats2half2_rn(v.z * linv, v.w * linv);
                uint2 pk;
                pk.x = *(uint32_t*)&h0; pk.y = *(uint32_t*)&h1;
                const long long m = orow0 + i * 16 + r;
                const int n = zh * 64 + j * 16 + c4 * 4;
                *(uint2*)(O + m * 768 + n) = pk;
            }
            __syncwarp();
        }
    }
}

// ---------------------------------------------------------------------------
// preps / LN / conv / scan
// ---------------------------------------------------------------------------
__global__ __launch_bounds__(256)
void transpose_f2h(const float* __restrict__ in, int ldi,
                   __half* __restrict__ out, int ldo, int R, int C)
{
    __shared__ float t[32][33];
    const int r0 = blockIdx.y * 32, c0 = blockIdx.x * 32;
    const int tx = threadIdx.x & 31, ty = threadIdx.x >> 5;
    #pragma unroll
    for (int i = 0; i < 32; i += 8) {
        const int r = r0 + ty + i, c = c0 + tx;
        t[ty + i][tx] = (r < R && c < C) ? in[(long long)r * ldi + c] : 0.f;
    }
    __syncthreads();
    #pragma unroll
    for (int i = 0; i < 32; i += 8) {
        const int r = c0 + ty + i, c = r0 + tx;
        if (r < C && c < R) out[(long long)r * ldo + c] = __float2half_rn(t[tx][ty + i]);
    }
}

__global__ __launch_bounds__(256)
void cast_f2h(const float* __restrict__ in, __half* __restrict__ out, int n)
{
    int i = blockIdx.x * 256 + threadIdx.x;
    if (i < n) out[i] = __float2half_rn(in[i]);
}

__global__ __launch_bounds__(256)
void dtw_prep(const float* __restrict__ dtw, __half* __restrict__ out)
{
    int i = blockIdx.x * 256 + threadIdx.x;
    int n = i >> 6, k = i & 63;
    out[i] = (k < 48) ? __float2half_rn(dtw[k * 1536 + n]) : __half(0.f);
}

__global__ __launch_bounds__(256)
void ln_kernel(const float* __restrict__ x, const float* __restrict__ g,
               const float* __restrict__ b, __half* __restrict__ y)
{
    long long row = blockIdx.x;
    const float* xr = x + row * 768;
    __half* yr = y + row * 768;
    int tid = threadIdx.x;

    float v0 = xr[tid], v1 = xr[tid + 256], v2 = xr[tid + 512];
    float s  = v0 + v1 + v2;
    float ss = v0 * v0 + v1 * v1 + v2 * v2;

    #pragma unroll
    for (int o = 16; o; o >>= 1) {
        s  += __shfl_xor_sync(0xffffffffu, s, o);
        ss += __shfl_xor_sync(0xffffffffu, ss, o);
    }
    __shared__ float sh_s[8], sh_ss[8];
    int w = tid >> 5, l = tid & 31;
    if (l == 0) { sh_s[w] = s; sh_ss[w] = ss; }
    __syncthreads();
    if (w == 0) {
        float s2  = (l < 8) ? sh_s[l]  : 0.f;
        float ss2 = (l < 8) ? sh_ss[l] : 0.f;
        #pragma unroll
        for (int o = 4; o; o >>= 1) {
            s2  += __shfl_xor_sync(0xffffffffu, s2, o);
            ss2 += __shfl_xor_sync(0xffffffffu, ss2, o);
        }
        if (l == 0) { sh_s[0] = s2; sh_ss[0] = ss2; }
    }
    __syncthreads();
    float mean = sh_s[0] * (1.0f / 768.0f);
    float var  = sh_ss[0] * (1.0f / 768.0f) - mean * mean;
    float rstd = rsqrtf(var + 1e-5f);

    yr[tid]       = __float2half_rn((v0 - mean) * rstd * g[tid]       + b[tid]);
    yr[tid + 256] = __float2half_rn((v1 - mean) * rstd * g[tid + 256] + b[tid + 256]);
    yr[tid + 512] = __float2half_rn((v2 - mean) * rstd * g[tid + 512] + b[tid + 512]);
}

// conv over half xz; scalar 1 channel/thread (measured best layout)
__global__ __launch_bounds__(256)
void conv_silu_kernel(const __half* __restrict__ xz, const float* __restrict__ cw,
                      const float* __restrict__ cb, __half* __restrict__ uh)
{
    int idx = blockIdx.x * 256 + threadIdx.x;
    int d   = idx % 1536;
    int tok = idx / 1536;
    int t   = tok & 1023;
    float acc = cb[d];
    const __half* base = xz + (long long)tok * 3072 + d;
    #pragma unroll
    for (int j = 0; j < 4; j++) {
        int tt = t - 3 + j;
        if (tt >= 0)
            acc = fmaf(__half2float(base[(long long)(j - 3) * 3072]), cw[d * 4 + j], acc);
    }
    uh[(long long)tok * 1536 + d] = __float2half_rn(silu_f(acc));
}

// scan over half u / half xz-res
__global__ __launch_bounds__(256)
void scan_kernel(const float* __restrict__ dt, const float* __restrict__ dbl,
                 const __half* __restrict__ u, const __half* __restrict__ xz,
                 const float* __restrict__ Alog, const float* __restrict__ Dp,
                 __half* __restrict__ y)
{
    int gg = blockIdx.x * 16 + (threadIdx.x >> 4);
    int s  = threadIdx.x & 15;
    int d  = gg % 1536, b = gg / 1536;

    float A  = -expf(Alog[d * 16 + s]);
    float Dv = Dp[d];
    float h  = 0.0f;
    long long tokbase = (long long)b * 1024;

    for (int t = 0; t < 1024; t++) {
        long long tok = tokbase + t;
        float dtv = dt[tok * 1536 + d];
        float uv  = __half2float(u[tok * 1536 + d]);
        float Bv  = dbl[tok * 80 + 48 + s];
        float Cv  = dbl[tok * 80 + 64 + s];
        float dA  = __expf(dtv * A);
        h = fmaf(dA, h, dtv * Bv * uv);
        float part = h * Cv;
        part += __shfl_xor_sync(0xffffffffu, part, 8, 16);
        part += __shfl_xor_sync(0xffffffffu, part, 4, 16);
        part += __shfl_xor_sync(0xffffffffu, part, 2, 16);
        part += __shfl_xor_sync(0xffffffffu, part, 1, 16);
        if (s == 0) {
            float rv = __half2float(xz[tok * 3072 + 1536 + d]);
            y[tok * 1536 + d] = __float2half_rn((part + uv * Dv) * silu_f(rv));
        }
    }
}

// ---------------------------------------------------------------------------
// Host orchestration
// ---------------------------------------------------------------------------
extern "C" void kernel_launch(void* const* d_in, const int* in_sizes, int n_in,
                              void* d_out, int out_size)
{
    const float* x    = (const float*)d_in[0];
    const float* n1g  = (const float*)d_in[1];
    const float* n1b  = (const float*)d_in[2];
    const float* aiw  = (const float*)d_in[3];
    const float* aib  = (const float*)d_in[4];
    const float* aow  = (const float*)d_in[5];
    const float* aob  = (const float*)d_in[6];
    const float* n2g  = (const float*)d_in[7];
    const float* n2b  = (const float*)d_in[8];
    const float* w1   = (const float*)d_in[9];
    const float* b1   = (const float*)d_in[10];
    const float* w2   = (const float*)d_in[11];
    const float* b2   = (const float*)d_in[12];
    const float* n3g  = (const float*)d_in[13];
    const float* n3b  = (const float*)d_in[14];
    const float* minw = (const float*)d_in[15];
    const float* cw   = (const float*)d_in[16];
    const float* cb   = (const float*)d_in[17];
    const float* xpw  = (const float*)d_in[18];
    const float* dtw  = (const float*)d_in[19];
    const float* dtbi = (const float*)d_in[20];
    const float* alog = (const float*)d_in[21];
    const float* dpar = (const float*)d_in[22];
    const float* mow  = (const float*)d_in[23];
    const float* gate = (const float*)d_in[24];
    float* out = (float*)d_out;

    __half *lnh, *qkvh, *attnh, *hh, *uh, *dblh, *yh, *wth;
    float  *dbl, *gdt;
    cudaGetSymbolAddress((void**)&lnh,   g_lnh);
    cudaGetSymbolAddress((void**)&qkvh,  g_qkvh);
    cudaGetSymbolAddress((void**)&attnh, g_attnh);
    cudaGetSymbolAddress((void**)&hh,    g_hh);
    cudaGetSymbolAddress((void**)&uh,    g_uh);
    cudaGetSymbolAddress((void**)&dbl,   g_dbl);
    cudaGetSymbolAddress((void**)&dblh,  g_dblh);
    cudaGetSymbolAddress((void**)&gdt,   g_dt);
    cudaGetSymbolAddress((void**)&yh,    g_yh);
    cudaGetSymbolAddress((void**)&wth,   g_wth);

    cudaFuncSetAttribute(tgemm<0, true>,  cudaFuncAttributeMaxDynamicSharedMemorySize, TG_SMEM);
    cudaFuncSetAttribute(tgemm<1, true>,  cudaFuncAttributeMaxDynamicSharedMemorySize, TG_SMEM);
    cudaFuncSetAttribute(tgemm<2, false>, cudaFuncAttributeMaxDynamicSharedMemorySize, TG_SMEM);
    cudaFuncSetAttribute(tgemm<3, true>,  cudaFuncAttributeMaxDynamicSharedMemorySize, TG_SMEM);
    cudaFuncSetAttribute(tgemm<4, false>, cudaFuncAttributeMaxDynamicSharedMemorySize, TG_SMEM);
    cudaFuncSetAttribute(tgemm<5, false>, cudaFuncAttributeMaxDynamicSharedMemorySize, TG_SMEM);
    cudaFuncSetAttribute(tgemm<6, false>, cudaFuncAttributeMaxDynamicSharedMemorySize, TG_SMEM);
    cudaFuncSetAttribute(flash_attn,      cudaFuncAttributeMaxDynamicSharedMemorySize, FA_SMEM);

    // launch order: 0 cast_aiw, 1 cast_aow, 2 ln1, 3 QKV gemm, 4 flash, 5 outproj
    cast_f2h<<<(2304 * 768 + 255) / 256, 256>>>(aiw, wth + WH_AIW, 2304 * 768);   // 0
    cast_f2h<<<(768 * 768 + 255) / 256, 256>>>(aow, wth + WH_AOW, 768 * 768);     // 1
    ln_kernel<<<8192, 256>>>(x, n1g, n1b, lnh);                                   // 2

    // 3) QKV = LN1 @ attn_in_w^T + b
    tgemm<1, true><<<dim3(18, 64, 1), 128, TG_SMEM>>>(
        lnh, 768, wth + WH_AIW, 768, qkvh, 2304,
        8192, 2304, 768, aib, nullptr, 0, 1.0f, nullptr, nullptr);

    // 4) fused attention
    flash_attn<<<dim3(8, 96), 128, FA_SMEM>>>(qkvh, attnh);

    // 5) x = x_in + O @ attn_out_w^T + b
    tgemm<2, false><<<dim3(6, 64, 1), 128, TG_SMEM>>>(
        attnh, 768, wth + WH_AOW, 768, out, 768,
        8192, 768, 768, aob, x, 768, 1.0f, nullptr, nullptr);

    // remaining weight preps
    transpose_f2h<<<dim3(96, 24, 1), 256>>>(w1, 3072, wth + WH_W1, 768, 768, 3072);
    transpose_f2h<<<dim3(24, 96, 1), 256>>>(w2, 768, wth + WH_W2, 3072, 3072, 768);
    transpose_f2h<<<dim3(96, 24, 1), 256>>>(minw, 3072, wth + WH_MIN, 768, 768, 3072);
    transpose_f2h<<<dim3(24, 48, 1), 256>>>(mow, 768, wth + WH_MOW, 1536, 1536, 768);
    transpose_f2h<<<dim3(3, 48, 1), 256>>>(xpw, 80, wth + WH_XPW, 1536, 1536, 80);
    dtw_prep<<<(1536 * 64 + 255) / 256, 256>>>(dtw, wth + WH_DTW);

    // LN2
    ln_kernel<<<8192, 256>>>(out, n2g, n2b, lnh);

    // H = gelu(LN2 @ W1 + b1) -> half
    tgemm<3, true><<<dim3(24, 64, 1), 128, TG_SMEM>>>(
        lnh, 768, wth + WH_W1, 768, hh, 3072,
        8192, 3072, 768, b1, nullptr, 0, 1.0f, nullptr, nullptr);

    // x += H @ W2 + b2
    tgemm<2, false><<<dim3(6, 64, 1), 128, TG_SMEM>>>(
        hh, 3072, wth + WH_W2, 3072, out, 768,
        8192, 768, 3072, b2, out, 768, 1.0f, nullptr, nullptr);

    // LN3
    ln_kernel<<<8192, 256>>>(out, n3g, n3b, lnh);

    // xz = LN3 @ m_in_w -> half (reuses hh)
    tgemm<0, true><<<dim3(24, 64, 1), 128, TG_SMEM>>>(
        lnh, 768, wth + WH_MIN, 768, hh, 3072,
        8192, 3072, 768, nullptr, nullptr, 0, 1.0f, nullptr, nullptr);

    // u = silu(conv(xz[:, :1536]) + cb) -> half
    conv_silu_kernel<<<49152, 256>>>(hh, cw, cb, uh);

    // dbl = u @ xproj_w -> float + fused padded-half dblh (EPI 6)
    tgemm<6, false><<<dim3(1, 64, 1), 128, TG_SMEM>>>(
        uh, 1536, wth + WH_XPW, 1536, dbl, 80,
        8192, 80, 1536, nullptr, nullptr, 0, 1.0f, nullptr, dblh);

    // dt = softplus(dbl48 @ dt_w + dt_b) -> float
    tgemm<4, false><<<dim3(12, 64, 1), 128, TG_SMEM>>>(
        dblh, 64, wth + WH_DTW, 64, gdt, 1536,
        8192, 1536, 64, dtbi, nullptr, 0, 1.0f, nullptr, nullptr);

    // selective scan + (u*D) + *silu(res) -> half
    scan_kernel<<<768, 256>>>(gdt, dbl, uh, hh, alog, dpar, yh);

    // out = x + sigmoid(gate) * (y @ m_out_w)
    tgemm<5, false><<<dim3(6, 64, 1), 128, TG_SMEM>>>(
        yh, 1536, wth + WH_MOW, 1536, out, 768,
        8192, 768, 1536, nullptr, out, 768, 1.0f, gate, nullptr);
}

// round 17
// speedup vs baseline: 1.1369x; 1.0172x over previous
#include <cuda_runtime.h>
#include <cuda_fp16.h>
#include <mma.h>
#include <cstdint>
#include <math.h>

using namespace nvcuda;

// ---------------------------------------------------------------------------
// MambaViTBlock: B=8, N=1024 (TOK=8192), D=768, NH=12 (dh=64), MLPH=3072,
//                DI=1536, DS=16, DTR=48, K=4
// Round 17: byte-exact R10 compute kernels (measured best 1903us). Only the
// three elementwise preps (aiw/aow casts + dtw prep) merged into prep_elem
// (no smem, no sync, block-range dispatch). Transposes stay separate
// (R16's fused-transpose kernel caused a capture-time sticky error).
// ---------------------------------------------------------------------------

__device__ __half g_lnh  [8192u * 768u];
__device__ __half g_qkvh [8192u * 2304u];
__device__ __half g_attnh[8192u * 768u];
__device__ __half g_hh   [8192u * 3072u];   // MLP hidden, then mamba xz (half)
__device__ __half g_uh   [8192u * 1536u];
__device__ float  g_dbl  [8192u * 80u];     // xproj out (dt_raw | B | C)
__device__ __half g_dblh [8192u * 64u];     // dbl[:, :48] padded to 64 (half)
__device__ float  g_dt   [8192u * 1536u];
__device__ __half g_yh   [8192u * 1536u];
__device__ __half g_wth  [10838016u];

#define WH_AIW  0u
#define WH_AOW  1769472u
#define WH_W1   2359296u
#define WH_W2   4718592u
#define WH_MIN  7077888u
#define WH_MOW  9437184u
#define WH_XPW  10616832u
#define WH_DTW  10739712u

__device__ __forceinline__ float gelu_exact(float v) {
    return 0.5f * v * (1.0f + erff(v * 0.7071067811865475f));
}
__device__ __forceinline__ float softplus_f(float v) {
    return fmaxf(v, 0.0f) + log1pf(expf(-fabsf(v)));
}
__device__ __forceinline__ float silu_f(float v) {
    return v / (1.0f + __expf(-v));
}

__device__ __forceinline__ uint32_t smem_u32(const void* p) {
    uint32_t a;
    asm("{ .reg .u64 t; cvta.to.shared.u64 t, %1; cvt.u32.u64 %0, t; }" : "=r"(a) : "l"(p));
    return a;
}
__device__ __forceinline__ void cp_async16(uint32_t dst, const void* src, int sz) {
    asm volatile("cp.async.ca.shared.global [%0], [%1], 16, %2;"
                 :: "r"(dst), "l"(src), "r"(sz));
}
__device__ __forceinline__ void cp_commit() { asm volatile("cp.async.commit_group;"); }
template<int N>
__device__ __forceinline__ void cp_wait() {
    asm volatile("cp.async.wait_group %0;" :: "n"(N));
}

#define TLDH 72

// ---------------------------------------------------------------------------
// Shared epilogue helper (per 16x16 patch; patch stride 16 floats)
// ---------------------------------------------------------------------------
template<int EPI, bool OH>
__device__ __forceinline__ void epi_patch(
    const float* patch, int lid, int mbase, int nfrag,
    float* Cf, __half* Ch, int ldc,
    const float* bias, const float* resid, int ldr,
    float scale, float gmul)
{
    #pragma unroll
    for (int q = 0; q < 2; q++) {
        const int idx = lid + 32 * q;
        const int r = idx >> 2, c4 = idx & 3;
        float4 v4 = *(const float4*)(patch + r * 16 + c4 * 4);
        const int n = nfrag + c4 * 4;
        const int m = mbase + r;
        float vv[4] = {v4.x, v4.y, v4.z, v4.w};
        #pragma unroll
        for (int qq = 0; qq < 4; qq++) {
            float t = vv[qq] * scale;
            if (EPI >= 1 && EPI <= 4) t += bias[n + qq];
            if (EPI == 3) t = gelu_exact(t);
            if (EPI == 4) t = softplus_f(t);
            if (EPI == 2) t += resid[(long long)m * ldr + n + qq];
            if (EPI == 5) t = resid[(long long)m * ldr + n + qq] + gmul * t;
            vv[qq] = t;
        }
        if (OH) {
            __half2 h0 = __floats2half2_rn(vv[0], vv[1]);
            __half2 h1 = __floats2half2_rn(vv[2], vv[3]);
            uint2 pk;
            pk.x = *(uint32_t*)&h0; pk.y = *(uint32_t*)&h1;
            *(uint2*)(Ch + (long long)m * ldc + n) = pk;
        } else {
            *(float4*)(Cf + (long long)m * ldc + n) =
                make_float4(vv[0], vv[1], vv[2], vv[3]);
        }
    }
}

// ---------------------------------------------------------------------------
// tgemm: 128x128 tile, 128 threads (4 warps of 64x64), BK=64, 2-stage.
// launch_bounds(128,2): 256-reg budget. (R10 structure — measured best.)
// ---------------------------------------------------------------------------
#define TG_SMEM (2 * 2 * 128 * TLDH * 2)   // 73728 B

template<int EPI, bool OH>
__global__ __launch_bounds__(128, 2)
void tgemm(const __half* __restrict__ A, int lda,
           const __half* __restrict__ B, int ldb,
           void* __restrict__ Cv, int ldc,
           int M, int N, int K,
           const float* __restrict__ bias,
           const float* __restrict__ resid, int ldr,
           float scale, const float* __restrict__ gatep)
{
    extern __shared__ __half smh[];
    const uint32_t sb = smem_u32(smh);

    const int tid = threadIdx.x;
    const int wid = tid >> 5, lid = tid & 31;
    const int warpM = wid & 1;
    const int warpN = wid >> 1;

    float*  Cf = (float*)Cv;
    __half* Ch = (__half*)Cv;

    const int m0 = blockIdx.y * 128, n0 = blockIdx.x * 128;
    const int NC = K / 64;

    wmma::fragment<wmma::accumulator, 16, 16, 16, float> acc[4][4];
    #pragma unroll
    for (int i = 0; i < 4; i++)
        #pragma unroll
        for (int j = 0; j < 4; j++) wmma::fill_fragment(acc[i][j], 0.0f);

    auto stage = [&](int c, int buf) {
        const int k0 = c * 64;
        const uint32_t offA = (uint32_t)buf * (2 * 128 * TLDH) * 2;
        const uint32_t offB = offA + (128 * TLDH) * 2;
        #pragma unroll
        for (int q = 0; q < 8; q++) {
            const int id  = q * 128 + tid;
            const int row = id >> 3, c16 = id & 7;
            const uint32_t so = (uint32_t)(row * (TLDH * 2) + c16 * 16);
            cp_async16(sb + offA + so,
                       A + (long long)(m0 + row) * lda + k0 + c16 * 8, 16);
            const bool bv = (n0 + row) < N;
            const __half* bsrc = bv ? (B + (long long)(n0 + row) * ldb + k0 + c16 * 8) : B;
            cp_async16(sb + offB + so, bsrc, bv ? 16 : 0);
        }
    };

    auto compute = [&](int buf) {
        const __half* Asb = smh + buf * (2 * 128 * TLDH);
        const __half* Bsb = Asb + 128 * TLDH;
        #pragma unroll
        for (int kk = 0; kk < 64; kk += 16) {
            wmma::fragment<wmma::matrix_a, 16, 16, 16, __half, wmma::row_major> af[4];
            #pragma unroll
            for (int i = 0; i < 4; i++)
                wmma::load_matrix_sync(af[i], Asb + (warpM * 64 + i * 16) * TLDH + kk, TLDH);
            wmma::fragment<wmma::matrix_b, 16, 16, 16, __half, wmma::col_major> bf[2];
            wmma::load_matrix_sync(bf[0], Bsb + (warpN * 64) * TLDH + kk, TLDH);
            #pragma unroll
            for (int j = 0; j < 4; j++) {
                if (j < 3)
                    wmma::load_matrix_sync(bf[(j + 1) & 1],
                        Bsb + (warpN * 64 + (j + 1) * 16) * TLDH + kk, TLDH);
                #pragma unroll
                for (int i = 0; i < 4; i++)
                    wmma::mma_sync(acc[i][j], af[i], bf[j & 1], acc[i][j]);
            }
        }
    };

    stage(0, 0);
    cp_commit();

    for (int c = 0; c < NC; c++) {
        if (c + 1 < NC) {
            stage(c + 1, (c + 1) & 1);
            cp_commit();
            cp_wait<1>();
        } else {
            cp_wait<0>();
        }
        __syncthreads();
        compute(c & 1);
        __syncthreads();
    }

    float gmul = 1.0f;
    if (EPI == 5) gmul = 1.0f / (1.0f + __expf(-gatep[0]));
    float* patch = (float*)smh + wid * 256;

    #pragma unroll
    for (int i = 0; i < 4; i++) {
        #pragma unroll
        for (int j = 0; j < 4; j++) {
            const int nfrag = n0 + warpN * 64 + j * 16;
            if (nfrag >= N) continue;
            wmma::store_matrix_sync(patch, acc[i][j], 16, wmma::mem_row_major);
            __syncwarp();
            epi_patch<EPI, OH>(patch, lid, m0 + warpM * 64 + i * 16, nfrag,
                               Cf, Ch, ldc, bias, resid, ldr, scale, gmul);
            __syncwarp();
        }
    }
}

// ---------------------------------------------------------------------------
// Fused flash attention (R10)
// ---------------------------------------------------------------------------
#define FA_SMEM 109056
#define FA_OFF_K 18432
#define FA_OFF_V 36864
#define FA_OFF_SF 55296
#define FA_OFF_PH 90112
#define FA_OFF_L 108544

__global__ __launch_bounds__(128, 2)
void flash_attn(const __half* __restrict__ qkv, __half* __restrict__ O)
{
    extern __shared__ __half smh[];
    const uint32_t sb = smem_u32(smh);
    char* smc = (char*)smh;

    const int tid = threadIdx.x;
    const int wid = tid >> 5, lid = tid & 31;
    const int qb = blockIdx.x;
    const int bh = blockIdx.y;
    const int zb = bh / 12, zh = bh % 12;

    const long long TQ = 1024LL * 2304LL;
    const __half* qbase = qkv + (long long)zb * TQ + zh * 64 + (long long)(qb * 128) * 2304;
    const __half* kbase = qkv + 768  + (long long)zb * TQ + zh * 64;
    const __half* vbase = qkv + 1536 + (long long)zb * TQ + zh * 64;

    #pragma unroll
    for (int q = 0; q < 8; q++) {
        const int id = q * 128 + tid;
        const int row = id >> 3, c16 = id & 7;
        cp_async16(sb + (uint32_t)(row * 144 + c16 * 16),
                   qbase + (long long)row * 2304 + c16 * 8, 16);
    }
    auto stageKV = [&](int it, int buf) {
        const long long r0 = (long long)(it * 64);
        const uint32_t offK = FA_OFF_K + (uint32_t)buf * 9216;
        const uint32_t offV = FA_OFF_V + (uint32_t)buf * 9216;
        #pragma unroll
        for (int q = 0; q < 4; q++) {
            const int id = q * 128 + tid;
            const int row = id >> 3, c16 = id & 7;
            const uint32_t so = (uint32_t)(row * 144 + c16 * 16);
            cp_async16(sb + offK + so, kbase + (r0 + row) * 2304 + c16 * 8, 16);
            cp_async16(sb + offV + so, vbase + (r0 + row) * 2304 + c16 * 8, 16);
        }
    };
    stageKV(0, 0);
    cp_commit();

    wmma::fragment<wmma::accumulator, 16, 16, 16, float> o_acc[2][4];
    #pragma unroll
    for (int i = 0; i < 2; i++)
        #pragma unroll
        for (int j = 0; j < 4; j++) wmma::fill_fragment(o_acc[i][j], 0.0f);
    float l = 0.0f;

    const __half* Qw = smh + (wid * 32) * TLDH;
    float* Sf = (float*)(smc + FA_OFF_SF) + wid * (32 * 68);
    __half* Ph = (__half*)(smc + FA_OFF_PH) + wid * (32 * TLDH);

    for (int it = 0; it < 16; it++) {
        if (it + 1 < 16) {
            stageKV(it + 1, (it + 1) & 1);
            cp_commit();
            cp_wait<1>();
        } else {
            cp_wait<0>();
        }
        __syncthreads();

        const __half* Ks = (const __half*)(smc + FA_OFF_K + (it & 1) * 9216);
        const __half* Vs = (const __half*)(smc + FA_OFF_V + (it & 1) * 9216);

        wmma::fragment<wmma::accumulator, 16, 16, 16, float> sa[2][4];
        #pragma unroll
        for (int i = 0; i < 2; i++)
            #pragma unroll
            for (int j = 0; j < 4; j++) wmma::fill_fragment(sa[i][j], 0.0f);
        #pragma unroll
        for (int kk = 0; kk < 4; kk++) {
            wmma::fragment<wmma::matrix_a, 16, 16, 16, __half, wmma::row_major> aq[2];
            wmma::load_matrix_sync(aq[0], Qw + kk * 16, TLDH);
            wmma::load_matrix_sync(aq[1], Qw + 16 * TLDH + kk * 16, TLDH);
            #pragma unroll
            for (int j = 0; j < 4; j++) {
                wmma::fragment<wmma::matrix_b, 16, 16, 16, __half, wmma::col_major> bk;
                wmma::load_matrix_sync(bk, Ks + (j * 16) * TLDH + kk * 16, TLDH);
                wmma::mma_sync(sa[0][j], aq[0], bk, sa[0][j]);
                wmma::mma_sync(sa[1][j], aq[1], bk, sa[1][j]);
            }
        }
        #pragma unroll
        for (int i = 0; i < 2; i++)
            #pragma unroll
            for (int j = 0; j < 4; j++) {
                #pragma unroll
                for (int e = 0; e < 8; e++)
                    sa[i][j].x[e] = __expf(sa[i][j].x[e] * 0.125f);
                wmma::store_matrix_sync(Sf + (i * 16) * 68 + j * 16, sa[i][j], 68,
                                        wmma::mem_row_major);
            }
        __syncwarp();
        {
            const float* srow = Sf + lid * 68;
            __half* prow = Ph + lid * TLDH;
            float sum = 0.0f;
            #pragma unroll
            for (int c = 0; c < 64; c += 4) {
                float4 v = *(const float4*)(srow + c);
                sum += (v.x + v.y) + (v.z + v.w);
                *(__half2*)(prow + c)     = __floats2half2_rn(v.x, v.y);
                *(__half2*)(prow + c + 2) = __floats2half2_rn(v.z, v.w);
            }
            l += sum;
        }
        __syncwarp();
        #pragma unroll
        for (int kk = 0; kk < 4; kk++) {
            wmma::fragment<wmma::matrix_a, 16, 16, 16, __half, wmma::row_major> ap[2];
            wmma::load_matrix_sync(ap[0], Ph + kk * 16, TLDH);
            wmma::load_matrix_sync(ap[1], Ph + 16 * TLDH + kk * 16, TLDH);
            #pragma unroll
            for (int j = 0; j < 4; j++) {
                wmma::fragment<wmma::matrix_b, 16, 16, 16, __half, wmma::row_major> bv;
                wmma::load_matrix_sync(bv, Vs + (kk * 16) * TLDH + j * 16, TLDH);
                wmma::mma_sync(o_acc[0][j], ap[0], bv, o_acc[0][j]);
                wmma::mma_sync(o_acc[1][j], ap[1], bv, o_acc[1][j]);
            }
        }
        __syncthreads();
    }

    float* l_sm = (float*)(smc + FA_OFF_L);
    l_sm[wid * 32 + lid] = l;
    __syncwarp();

    float* patch = Sf;
    const long long orow0 = (long long)zb * 1024 + qb * 128 + wid * 32;
    #pragma unroll
    for (int i = 0; i < 2; i++) {
        #pragma unroll
        for (int j = 0; j < 4; j++) {
            wmma::store_matrix_sync(patch, o_acc[i][j], 16, wmma::mem_row_major);
            __syncwarp();
            #pragma unroll
            for (int q = 0; q < 2; q++) {
                const int idx = lid + 32 * q;
                const int r = idx >> 2, c4 = idx & 3;
                float4 v = *(const float4*)(patch + r * 16 + c4 * 4);
                const float linv = 1.0f / l_sm[wid * 32 + i * 16 + r];
                __half2 h0 = __floats2half2_rn(v.x * linv, v.y * linv);
                __half2 h1 = __floats2half2_rn(v.z * linv, v.w * linv);
                uint2 pk;
                pk.x = *(uint32_t*)&h0; pk.y = *(uint32_t*)&h1;
                const long long m = orow0 + i * 16 + r;
                const int n = zh * 64 + j * 16 + c4 * 4;
                *(uint2*)(O + m * 768 + n) = pk;
            }
            __syncwarp();
        }
    }
}

// ---------------------------------------------------------------------------
// preps / LN / conv / scan (R10 kernels; only the elementwise preps merged)
// ---------------------------------------------------------------------------

// merged elementwise preps: aiw cast (6912 blocks) | aow cast (2304) | dtw (384)
__global__ __launch_bounds__(256)
void prep_elem(const float* __restrict__ aiw, const float* __restrict__ aow,
               const float* __restrict__ dtw, __half* __restrict__ wth)
{
    const int b = blockIdx.x, tid = threadIdx.x;
    if (b < 6912) {                       // aiw: 2304*768 = 6912*256 exactly
        const int i = b * 256 + tid;
        wth[WH_AIW + i] = __float2half_rn(aiw[i]);
    } else if (b < 9216) {                // aow: 768*768 = 2304*256 exactly
        const int i = (b - 6912) * 256 + tid;
        wth[WH_AOW + i] = __float2half_rn(aow[i]);
    } else {                              // dtw: 1536*64 = 384*256 exactly
        const int i = (b - 9216) * 256 + tid;
        const int n = i >> 6, k = i & 63;
        wth[WH_DTW + i] = (k < 48) ? __float2half_rn(dtw[k * 1536 + n]) : __half(0.f);
    }
}

__global__ __launch_bounds__(256)
void transpose_f2h(const float* __restrict__ in, int ldi,
                   __half* __restrict__ out, int ldo, int R, int C)
{
    __shared__ float t[32][33];
    const int r0 = blockIdx.y * 32, c0 = blockIdx.x * 32;
    const int tx = threadIdx.x & 31, ty = threadIdx.x >> 5;
    #pragma unroll
    for (int i = 0; i < 32; i += 8) {
        const int r = r0 + ty + i, c = c0 + tx;
        t[ty + i][tx] = (r < R && c < C) ? in[(long long)r * ldi + c] : 0.f;
    }
    __syncthreads();
    #pragma unroll
    for (int i = 0; i < 32; i += 8) {
        const int r = c0 + ty + i, c = r0 + tx;
        if (r < C && c < R) out[(long long)r * ldo + c] = __float2half_rn(t[tx][ty + i]);
    }
}

__global__ __launch_bounds__(256)
void dbl_prep(const float* __restrict__ dbl, __half* __restrict__ out)
{
    int i = blockIdx.x * 256 + threadIdx.x;
    int r = i >> 6, c = i & 63;
    out[i] = (c < 48) ? __float2half_rn(dbl[r * 80 + c]) : __half(0.f);
}

__global__ __launch_bounds__(256)
void ln_kernel(const float* __restrict__ x, const float* __restrict__ g,
               const float* __restrict__ b, __half* __restrict__ y)
{
    long long row = blockIdx.x;
    const float* xr = x + row * 768;
    __half* yr = y + row * 768;
    int tid = threadIdx.x;

    float v0 = xr[tid], v1 = xr[tid + 256], v2 = xr[tid + 512];
    float s  = v0 + v1 + v2;
    float ss = v0 * v0 + v1 * v1 + v2 * v2;

    #pragma unroll
    for (int o = 16; o; o >>= 1) {
        s  += __shfl_xor_sync(0xffffffffu, s, o);
        ss += __shfl_xor_sync(0xffffffffu, ss, o);
    }
    __shared__ float sh_s[8], sh_ss[8];
    int w = tid >> 5, l = tid & 31;
    if (l == 0) { sh_s[w] = s; sh_ss[w] = ss; }
    __syncthreads();
    if (w == 0) {
        float s2  = (l < 8) ? sh_s[l]  : 0.f;
        float ss2 = (l < 8) ? sh_ss[l] : 0.f;
        #pragma unroll
        for (int o = 4; o; o >>= 1) {
            s2  += __shfl_xor_sync(0xffffffffu, s2, o);
            ss2 += __shfl_xor_sync(0xffffffffu, ss2, o);
        }
        if (l == 0) { sh_s[0] = s2; sh_ss[0] = ss2; }
    }
    __syncthreads();
    float mean = sh_s[0] * (1.0f / 768.0f);
    float var  = sh_ss[0] * (1.0f / 768.0f) - mean * mean;
    float rstd = rsqrtf(var + 1e-5f);

    yr[tid]       = __float2half_rn((v0 - mean) * rstd * g[tid]       + b[tid]);
    yr[tid + 256] = __float2half_rn((v1 - mean) * rstd * g[tid + 256] + b[tid + 256]);
    yr[tid + 512] = __float2half_rn((v2 - mean) * rstd * g[tid + 512] + b[tid + 512]);
}

// conv over half xz; scalar 1 channel/thread (measured best layout)
__global__ __launch_bounds__(256)
void conv_silu_kernel(const __half* __restrict__ xz, const float* __restrict__ cw,
                      const float* __restrict__ cb, __half* __restrict__ uh)
{
    int idx = blockIdx.x * 256 + threadIdx.x;
    int d   = idx % 1536;
    int tok = idx / 1536;
    int t   = tok & 1023;
    float acc = cb[d];
    const __half* base = xz + (long long)tok * 3072 + d;
    #pragma unroll
    for (int j = 0; j < 4; j++) {
        int tt = t - 3 + j;
        if (tt >= 0)
            acc = fmaf(__half2float(base[(long long)(j - 3) * 3072]), cw[d * 4 + j], acc);
    }
    uh[(long long)tok * 1536 + d] = __float2half_rn(silu_f(acc));
}

// scan over half u / half xz-res
__global__ __launch_bounds__(256)
void scan_kernel(const float* __restrict__ dt, const float* __restrict__ dbl,
                 const __half* __restrict__ u, const __half* __restrict__ xz,
                 const float* __restrict__ Alog, const float* __restrict__ Dp,
                 __half* __restrict__ y)
{
    int gg = blockIdx.x * 16 + (threadIdx.x >> 4);
    int s  = threadIdx.x & 15;
    int d  = gg % 1536, b = gg / 1536;

    float A  = -expf(Alog[d * 16 + s]);
    float Dv = Dp[d];
    float h  = 0.0f;
    long long tokbase = (long long)b * 1024;

    for (int t = 0; t < 1024; t++) {
        long long tok = tokbase + t;
        float dtv = dt[tok * 1536 + d];
        float uv  = __half2float(u[tok * 1536 + d]);
        float Bv  = dbl[tok * 80 + 48 + s];
        float Cv  = dbl[tok * 80 + 64 + s];
        float dA  = __expf(dtv * A);
        h = fmaf(dA, h, dtv * Bv * uv);
        float part = h * Cv;
        part += __shfl_xor_sync(0xffffffffu, part, 8, 16);
        part += __shfl_xor_sync(0xffffffffu, part, 4, 16);
        part += __shfl_xor_sync(0xffffffffu, part, 2, 16);
        part += __shfl_xor_sync(0xffffffffu, part, 1, 16);
        if (s == 0) {
            float rv = __half2float(xz[tok * 3072 + 1536 + d]);
            y[tok * 1536 + d] = __float2half_rn((part + uv * Dv) * silu_f(rv));
        }
    }
}

// ---------------------------------------------------------------------------
// Host orchestration
// ---------------------------------------------------------------------------
extern "C" void kernel_launch(void* const* d_in, const int* in_sizes, int n_in,
                              void* d_out, int out_size)
{
    const float* x    = (const float*)d_in[0];
    const float* n1g  = (const float*)d_in[1];
    const float* n1b  = (const float*)d_in[2];
    const float* aiw  = (const float*)d_in[3];
    const float* aib  = (const float*)d_in[4];
    const float* aow  = (const float*)d_in[5];
    const float* aob  = (const float*)d_in[6];
    const float* n2g  = (const float*)d_in[7];
    const float* n2b  = (const float*)d_in[8];
    const float* w1   = (const float*)d_in[9];
    const float* b1   = (const float*)d_in[10];
    const float* w2   = (const float*)d_in[11];
    const float* b2   = (const float*)d_in[12];
    const float* n3g  = (const float*)d_in[13];
    const float* n3b  = (const float*)d_in[14];
    const float* minw = (const float*)d_in[15];
    const float* cw   = (const float*)d_in[16];
    const float* cb   = (const float*)d_in[17];
    const float* xpw  = (const float*)d_in[18];
    const float* dtw  = (const float*)d_in[19];
    const float* dtbi = (const float*)d_in[20];
    const float* alog = (const float*)d_in[21];
    const float* dpar = (const float*)d_in[22];
    const float* mow  = (const float*)d_in[23];
    const float* gate = (const float*)d_in[24];
    float* out = (float*)d_out;

    __half *lnh, *qkvh, *attnh, *hh, *uh, *dblh, *yh, *wth;
    float  *dbl, *gdt;
    cudaGetSymbolAddress((void**)&lnh,   g_lnh);
    cudaGetSymbolAddress((void**)&qkvh,  g_qkvh);
    cudaGetSymbolAddress((void**)&attnh, g_attnh);
    cudaGetSymbolAddress((void**)&hh,    g_hh);
    cudaGetSymbolAddress((void**)&uh,    g_uh);
    cudaGetSymbolAddress((void**)&dbl,   g_dbl);
    cudaGetSymbolAddress((void**)&dblh,  g_dblh);
    cudaGetSymbolAddress((void**)&gdt,   g_dt);
    cudaGetSymbolAddress((void**)&yh,    g_yh);
    cudaGetSymbolAddress((void**)&wth,   g_wth);

    cudaFuncSetAttribute(tgemm<0, true>,  cudaFuncAttributeMaxDynamicSharedMemorySize, TG_SMEM);
    cudaFuncSetAttribute(tgemm<0, false>, cudaFuncAttributeMaxDynamicSharedMemorySize, TG_SMEM);
    cudaFuncSetAttribute(tgemm<1, true>,  cudaFuncAttributeMaxDynamicSharedMemorySize, TG_SMEM);
    cudaFuncSetAttribute(tgemm<2, false>, cudaFuncAttributeMaxDynamicSharedMemorySize, TG_SMEM);
    cudaFuncSetAttribute(tgemm<3, true>,  cudaFuncAttributeMaxDynamicSharedMemorySize, TG_SMEM);
    cudaFuncSetAttribute(tgemm<4, false>, cudaFuncAttributeMaxDynamicSharedMemorySize, TG_SMEM);
    cudaFuncSetAttribute(tgemm<5, false>, cudaFuncAttributeMaxDynamicSharedMemorySize, TG_SMEM);
    cudaFuncSetAttribute(flash_attn,      cudaFuncAttributeMaxDynamicSharedMemorySize, FA_SMEM);

    // launch order: 0 prep_elem, 1 ln1, 2 QKV gemm, 3 flash, 4 outproj, ...
    prep_elem<<<9600, 256>>>(aiw, aow, dtw, wth);                 // 0
    ln_kernel<<<8192, 256>>>(x, n1g, n1b, lnh);                   // 1

    // 2) QKV = LN1 @ attn_in_w^T + b
    tgemm<1, true><<<dim3(18, 64, 1), 128, TG_SMEM>>>(
        lnh, 768, wth + WH_AIW, 768, qkvh, 2304,
        8192, 2304, 768, aib, nullptr, 0, 1.0f, nullptr);

    // 3) fused attention
    flash_attn<<<dim3(8, 96), 128, FA_SMEM>>>(qkvh, attnh);

    // 4) x = x_in + O @ attn_out_w^T + b
    tgemm<2, false><<<dim3(6, 64, 1), 128, TG_SMEM>>>(
        attnh, 768, wth + WH_AOW, 768, out, 768,
        8192, 768, 768, aob, x, 768, 1.0f, nullptr);

    // remaining weight transposes (proven kernels, kept separate)
    transpose_f2h<<<dim3(96, 24, 1), 256>>>(w1, 3072, wth + WH_W1, 768, 768, 3072);
    transpose_f2h<<<dim3(24, 96, 1), 256>>>(w2, 768, wth + WH_W2, 3072, 3072, 768);
    transpose_f2h<<<dim3(96, 24, 1), 256>>>(minw, 3072, wth + WH_MIN, 768, 768, 3072);
    transpose_f2h<<<dim3(24, 48, 1), 256>>>(mow, 768, wth + WH_MOW, 1536, 1536, 768);
    transpose_f2h<<<dim3(3, 48, 1), 256>>>(xpw, 80, wth + WH_XPW, 1536, 1536, 80);

    // LN2
    ln_kernel<<<8192, 256>>>(out, n2g, n2b, lnh);

    // H = gelu(LN2 @ W1 + b1) -> half
    tgemm<3, true><<<dim3(24, 64, 1), 128, TG_SMEM>>>(
        lnh, 768, wth + WH_W1, 768, hh, 3072,
        8192, 3072, 768, b1, nullptr, 0, 1.0f, nullptr);

    // x += H @ W2 + b2
    tgemm<2, false><<<dim3(6, 64, 1), 128, TG_SMEM>>>(
        hh, 3072, wth + WH_W2, 3072, out, 768,
        8192, 768, 3072, b2, out, 768, 1.0f, nullptr);

    // LN3
    ln_kernel<<<8192, 256>>>(out, n3g, n3b, lnh);

    // xz = LN3 @ m_in_w -> half (reuses hh)
    tgemm<0, true><<<dim3(24, 64, 1), 128, TG_SMEM>>>(
        lnh, 768, wth + WH_MIN, 768, hh, 3072,
        8192, 3072, 768, nullptr, nullptr, 0, 1.0f, nullptr);

    // u = silu(conv(xz[:, :1536]) + cb) -> half
    conv_silu_kernel<<<49152, 256>>>(hh, cw, cb, uh);

    // dbl = u @ xproj_w -> float
    tgemm<0, false><<<dim3(1, 64, 1), 128, TG_SMEM>>>(
        uh, 1536, wth + WH_XPW, 1536, dbl, 80,
        8192, 80, 1536, nullptr, nullptr, 0, 1.0f, nullptr);

    // dbl[:, :48] -> half padded [8192,64]
    dbl_prep<<<(8192 * 64 + 255) / 256, 256>>>(dbl, dblh);

    // dt = softplus(dbl48 @ dt_w + dt_b) -> float
    tgemm<4, false><<<dim3(12, 64, 1), 128, TG_SMEM>>>(
        dblh, 64, wth + WH_DTW, 64, gdt, 1536,
        8192, 1536, 64, dtbi, nullptr, 0, 1.0f, nullptr);

    // selective scan + (u*D) + *silu(res) -> half
    scan_kernel<<<768, 256>>>(gdt, dbl, uh, hh, alog, dpar, yh);

    // out = x + sigmoid(gate) * (y @ m_out_w)
    tgemm<5, false><<<dim3(6, 64, 1), 128, TG_SMEM>>>(
        yh, 1536, wth + WH_MOW, 1536, out, 768,
        8192, 768, 1536, nullptr, out, 768, 1.0f, gate);
}